// round 1
// baseline (speedup 1.0000x reference)
#include <cuda_runtime.h>
#include <math.h>

#define BB 16
#define NN 1024
#define FIN 256
#define FOUT 256
#define HH 8
#define ALPHA 0.2f

// Scratch (device globals; no allocations allowed)
__device__ float g_Wh[(size_t)BB * HH * NN * FOUT];   // [b,h,n,o]  128 MB
__device__ float g_ei[BB * HH * NN];                  // a1 . Wh_i
__device__ float g_ejb[BB * HH * NN];                 // a2 . Wh_j + bA[h]

// ---------------------------------------------------------------------------
// Kernel 1: Wh = h @ W^T + bW
// C[m, j] = sum_f A[m,f] * Wf[j,f],  m = b*NN+n (16384), j = h*FOUT+o (2048)
// BM=128, BN=128, BK=16, 256 threads, 8x8 microtile.
// ---------------------------------------------------------------------------
__global__ void __launch_bounds__(256) gemm1_kernel(const float* __restrict__ A,
                                                    const float* __restrict__ Wf,
                                                    const float* __restrict__ bW)
{
    __shared__ float As[16][132];
    __shared__ float Bs[16][132];

    const int tid = threadIdx.x;
    const int tx = tid & 15;       // col group
    const int ty = tid >> 4;       // row group
    const int m0 = blockIdx.x * 128;
    const int j0 = blockIdx.y * 128;

    float acc[8][8];
#pragma unroll
    for (int i = 0; i < 8; i++)
#pragma unroll
        for (int j = 0; j < 8; j++) acc[i][j] = 0.f;

    const int lrow = tid >> 1;          // 0..127
    const int lk   = (tid & 1) * 8;     // 0 or 8

    const float* aptr = A  + (size_t)(m0 + lrow) * FIN + lk;
    const float* bptr = Wf + (size_t)(j0 + lrow) * FIN + lk;

    for (int k0 = 0; k0 < FIN; k0 += 16) {
        float4 av0 = *(const float4*)(aptr + k0);
        float4 av1 = *(const float4*)(aptr + k0 + 4);
        float4 bv0 = *(const float4*)(bptr + k0);
        float4 bv1 = *(const float4*)(bptr + k0 + 4);
        __syncthreads();
        As[lk + 0][lrow] = av0.x; As[lk + 1][lrow] = av0.y;
        As[lk + 2][lrow] = av0.z; As[lk + 3][lrow] = av0.w;
        As[lk + 4][lrow] = av1.x; As[lk + 5][lrow] = av1.y;
        As[lk + 6][lrow] = av1.z; As[lk + 7][lrow] = av1.w;
        Bs[lk + 0][lrow] = bv0.x; Bs[lk + 1][lrow] = bv0.y;
        Bs[lk + 2][lrow] = bv0.z; Bs[lk + 3][lrow] = bv0.w;
        Bs[lk + 4][lrow] = bv1.x; Bs[lk + 5][lrow] = bv1.y;
        Bs[lk + 6][lrow] = bv1.z; Bs[lk + 7][lrow] = bv1.w;
        __syncthreads();
#pragma unroll
        for (int k = 0; k < 16; k++) {
            float a[8], b[8];
            *(float4*)&a[0] = *(const float4*)&As[k][ty * 8];
            *(float4*)&a[4] = *(const float4*)&As[k][ty * 8 + 4];
            *(float4*)&b[0] = *(const float4*)&Bs[k][tx * 8];
            *(float4*)&b[4] = *(const float4*)&Bs[k][tx * 8 + 4];
#pragma unroll
            for (int i = 0; i < 8; i++)
#pragma unroll
                for (int j = 0; j < 8; j++)
                    acc[i][j] = fmaf(a[i], b[j], acc[i][j]);
        }
    }

    // Epilogue: add bias, scatter to g_Wh[b][h][n][o]
    const int col = j0 + tx * 8;           // 8 consecutive cols, same head
    const int hh = col >> 8;
    const int oo = col & 255;
    float4 bw0 = *(const float4*)(bW + col);
    float4 bw1 = *(const float4*)(bW + col + 4);
#pragma unroll
    for (int i = 0; i < 8; i++) {
        int mrow = m0 + ty * 8 + i;
        int b = mrow >> 10, n = mrow & 1023;
        float* dst = g_Wh + (((size_t)(b * HH + hh) * NN + n) * FOUT + oo);
        float4 v0, v1;
        v0.x = acc[i][0] + bw0.x; v0.y = acc[i][1] + bw0.y;
        v0.z = acc[i][2] + bw0.z; v0.w = acc[i][3] + bw0.w;
        v1.x = acc[i][4] + bw1.x; v1.y = acc[i][5] + bw1.y;
        v1.z = acc[i][6] + bw1.z; v1.w = acc[i][7] + bw1.w;
        *(float4*)(dst)     = v0;
        *(float4*)(dst + 4) = v1;
    }
}

// ---------------------------------------------------------------------------
// Kernel 2: ei[row] = Wh[row,:] . a1[h,:] ;  ejb[row] = Wh[row,:] . a2[h,:] + bA[h]
// One warp per row (row = (b*HH+h)*NN + n), 8 warps/block.
// ---------------------------------------------------------------------------
__global__ void __launch_bounds__(256) score_kernel(const float* __restrict__ a1,
                                                    const float* __restrict__ a2,
                                                    const float* __restrict__ bA)
{
    const int warp = threadIdx.x >> 5;
    const int lane = threadIdx.x & 31;
    const int row = blockIdx.x * 8 + warp;       // 0 .. BB*HH*NN-1
    const int h = (row >> 10) & (HH - 1);        // (row / NN) % HH

    const float4* wr = (const float4*)(g_Wh + (size_t)row * FOUT);
    const float4* p1 = (const float4*)(a1 + h * FOUT);
    const float4* p2 = (const float4*)(a2 + h * FOUT);

    float s1 = 0.f, s2 = 0.f;
#pragma unroll
    for (int u = 0; u < 2; u++) {
        float4 v = wr[lane + u * 32];
        float4 x = p1[lane + u * 32];
        float4 y = p2[lane + u * 32];
        s1 += v.x * x.x + v.y * x.y + v.z * x.z + v.w * x.w;
        s2 += v.x * y.x + v.y * y.y + v.z * y.z + v.w * y.w;
    }
#pragma unroll
    for (int off = 16; off > 0; off >>= 1) {
        s1 += __shfl_xor_sync(0xffffffffu, s1, off);
        s2 += __shfl_xor_sync(0xffffffffu, s2, off);
    }
    if (lane == 0) {
        g_ei[row] = s1;
        g_ejb[row] = s2 + bA[h];
    }
}

// ---------------------------------------------------------------------------
// Kernel 3: flash-style attention + relu + sigmoid + head-concat store.
// Block = one (b,h, 64-row tile). 256 threads: thread (rg,cg) owns rows
// rg*4..rg*4+3 and cols cg*16..cg*16+15 of the accumulator.
// ---------------------------------------------------------------------------
__device__ __forceinline__ void fma4(float4& a, float p, const float4& w) {
    a.x = fmaf(p, w.x, a.x); a.y = fmaf(p, w.y, a.y);
    a.z = fmaf(p, w.z, a.z); a.w = fmaf(p, w.w, a.w);
}

__global__ void __launch_bounds__(256, 2) attn_kernel(float* __restrict__ out)
{
    extern __shared__ float sm[];
    float4* Whs4 = (float4*)sm;                 // [64 j][64 float4] = [64][256] f
    float*  ps   = sm + 64 * 256;               // [64 j][68] (row-padded)
    float*  sred = ps + 64 * 68;                // [64 r][16]
    float*  ejs  = sred + 64 * 16;              // [64]

    const int tid = threadIdx.x;
    const int cg = tid & 15;
    const int rg = tid >> 4;
    const int r0 = rg * 4;
    const int it = blockIdx.x & 15;             // row tile
    const int bh = blockIdx.x >> 4;             // 0..127

    const float* __restrict__ Whbh = g_Wh + (size_t)bh * (NN * FOUT);
    const float* __restrict__ eirow = g_ei + bh * NN + it * 64;
    const float* __restrict__ ejrow = g_ejb + bh * NN;

    float eir[4];
#pragma unroll
    for (int rr = 0; rr < 4; rr++) eir[rr] = eirow[r0 + rr];

    float m[4], l[4];
    float4 acc[4][4];
#pragma unroll
    for (int rr = 0; rr < 4; rr++) {
        m[rr] = -1e30f; l[rr] = 0.f;
#pragma unroll
        for (int c = 0; c < 4; c++) acc[rr][c] = make_float4(0.f, 0.f, 0.f, 0.f);
    }

    for (int jt = 0; jt < 16; jt++) {
        // Stage Wh j-tile [64][256] into smem (coalesced float4)
        const float4* src = (const float4*)(Whbh + (size_t)jt * 64 * FOUT);
#pragma unroll
        for (int u = 0; u < 16; u++)
            Whs4[tid + u * 256] = src[tid + u * 256];
        if (tid < 64) ejs[tid] = ejrow[jt * 64 + tid];
        __syncthreads();

        // Scores: 4 rows x 4 local j (j_local = cg*4+jj)
        float sc[4][4], pm[4];
#pragma unroll
        for (int rr = 0; rr < 4; rr++) {
            pm[rr] = -1e30f;
#pragma unroll
            for (int jj = 0; jj < 4; jj++) {
                float e = eir[rr] + ejs[cg * 4 + jj];
                e = (e > 0.f) ? e : (ALPHA * e);
                sc[rr][jj] = e;
                pm[rr] = fmaxf(pm[rr], e);
            }
        }
#pragma unroll
        for (int rr = 0; rr < 4; rr++) sred[(r0 + rr) * 16 + cg] = pm[rr];
        __syncthreads();

#pragma unroll
        for (int rr = 0; rr < 4; rr++) {
            float mx = m[rr];
#pragma unroll
            for (int c = 0; c < 16; c++) mx = fmaxf(mx, sred[(r0 + rr) * 16 + c]);
            float scale = __expf(m[rr] - mx);
            m[rr] = mx;
            float lp = 0.f;
#pragma unroll
            for (int jj = 0; jj < 4; jj++) {
                float p = __expf(sc[rr][jj] - mx);
                ps[(cg * 4 + jj) * 68 + r0 + rr] = p;
                lp += p;
            }
            l[rr] = l[rr] * scale + lp;
#pragma unroll
            for (int c = 0; c < 4; c++) {
                acc[rr][c].x *= scale; acc[rr][c].y *= scale;
                acc[rr][c].z *= scale; acc[rr][c].w *= scale;
            }
        }
        __syncthreads();

        // acc += P @ Wh  (each Wh float4 reused across 4 rows)
#pragma unroll 4
        for (int j = 0; j < 64; j++) {
            float4 p4 = *(const float4*)&ps[j * 68 + r0];
            const float4* wp = Whs4 + j * 64 + cg * 4;
            float4 w0 = wp[0], w1 = wp[1], w2 = wp[2], w3 = wp[3];
            float pr[4] = {p4.x, p4.y, p4.z, p4.w};
#pragma unroll
            for (int rr = 0; rr < 4; rr++) {
                fma4(acc[rr][0], pr[rr], w0);
                fma4(acc[rr][1], pr[rr], w1);
                fma4(acc[rr][2], pr[rr], w2);
                fma4(acc[rr][3], pr[rr], w3);
            }
        }
        __syncthreads();
    }

    // Reduce l across the 16 col-group threads of each row
#pragma unroll
    for (int rr = 0; rr < 4; rr++) sred[(r0 + rr) * 16 + cg] = l[rr];
    __syncthreads();
    float linv[4];
#pragma unroll
    for (int rr = 0; rr < 4; rr++) {
        float s = 0.f;
#pragma unroll
        for (int c = 0; c < 16; c++) s += sred[(r0 + rr) * 16 + c];
        linv[rr] = 1.f / s;
    }

    // sigmoid(relu(acc / l)) -> out[b][n][h*FOUT + col]
    const int b = bh >> 3, h = bh & 7;
#pragma unroll
    for (int rr = 0; rr < 4; rr++) {
        int n = it * 64 + r0 + rr;
        float4* op = (float4*)(out + (size_t)(b * NN + n) * (HH * FOUT)
                                   + h * FOUT + cg * 16);
#pragma unroll
        for (int c = 0; c < 4; c++) {
            float4 v = acc[rr][c];
            float x0 = fmaxf(v.x * linv[rr], 0.f);
            float x1 = fmaxf(v.y * linv[rr], 0.f);
            float x2 = fmaxf(v.z * linv[rr], 0.f);
            float x3 = fmaxf(v.w * linv[rr], 0.f);
            v.x = 1.f / (1.f + __expf(-x0));
            v.y = 1.f / (1.f + __expf(-x1));
            v.z = 1.f / (1.f + __expf(-x2));
            v.w = 1.f / (1.f + __expf(-x3));
            op[c] = v;
        }
    }
}

// ---------------------------------------------------------------------------
extern "C" void kernel_launch(void* const* d_in, const int* in_sizes, int n_in,
                              void* d_out, int out_size)
{
    (void)in_sizes; (void)n_in; (void)out_size;
    const float* h_in = (const float*)d_in[0];  // [B,N,FIN]
    const float* W    = (const float*)d_in[1];  // [H,FOUT,FIN] == [2048,256]
    const float* bW   = (const float*)d_in[2];  // [H,FOUT]     == [2048]
    const float* a1   = (const float*)d_in[3];  // [H,FOUT]
    const float* a2   = (const float*)d_in[4];  // [H,FOUT]
    const float* bA   = (const float*)d_in[5];  // [H]
    float* out = (float*)d_out;                 // [B,N,H*FOUT] fp32

    // 1) Wh projection GEMM
    gemm1_kernel<<<dim3((BB * NN) / 128, (HH * FOUT) / 128), 256>>>(h_in, W, bW);

    // 2) score projections
    score_kernel<<<(BB * HH * NN) / 8, 256>>>(a1, a2, bA);

    // 3) flash attention + epilogue
    const int SMEM = (64 * 256 + 64 * 68 + 64 * 16 + 64) * (int)sizeof(float);
    cudaFuncSetAttribute(attn_kernel, cudaFuncAttributeMaxDynamicSharedMemorySize, SMEM);
    attn_kernel<<<BB * HH * (NN / 64), 256, SMEM>>>(out);
}

// round 3
// speedup vs baseline: 3.2539x; 3.2539x over previous
#include <cuda_runtime.h>
#include <stdint.h>
#include <math.h>

#define BB 16
#define NN 1024
#define FIN 256
#define FOUT 256
#define HH 8
#define ALPHA 0.2f

// Scratch (device globals; no allocations allowed)
__device__ float g_Wh[(size_t)BB * HH * NN * FOUT];   // [bh][n][o]
__device__ float g_ei[BB * HH * NN];                  // a1 . Wh_i
__device__ float g_ejb[BB * HH * NN];                 // a2 . Wh_j + bA[h]

// ---------------------------------------------------------------------------
// Kernel 1: Wh = h @ W^T + bW   (fp32 SIMT, proven)
// ---------------------------------------------------------------------------
__global__ void __launch_bounds__(256) gemm1_kernel(const float* __restrict__ A,
                                                    const float* __restrict__ Wf,
                                                    const float* __restrict__ bW)
{
    __shared__ float As[16][132];
    __shared__ float Bs[16][132];

    const int tid = threadIdx.x;
    const int tx = tid & 15;
    const int ty = tid >> 4;
    const int m0 = blockIdx.x * 128;
    const int j0 = blockIdx.y * 128;

    float acc[8][8];
#pragma unroll
    for (int i = 0; i < 8; i++)
#pragma unroll
        for (int j = 0; j < 8; j++) acc[i][j] = 0.f;

    const int lrow = tid >> 1;
    const int lk   = (tid & 1) * 8;

    const float* aptr = A  + (size_t)(m0 + lrow) * FIN + lk;
    const float* bptr = Wf + (size_t)(j0 + lrow) * FIN + lk;

    for (int k0 = 0; k0 < FIN; k0 += 16) {
        float4 av0 = *(const float4*)(aptr + k0);
        float4 av1 = *(const float4*)(aptr + k0 + 4);
        float4 bv0 = *(const float4*)(bptr + k0);
        float4 bv1 = *(const float4*)(bptr + k0 + 4);
        __syncthreads();
        As[lk + 0][lrow] = av0.x; As[lk + 1][lrow] = av0.y;
        As[lk + 2][lrow] = av0.z; As[lk + 3][lrow] = av0.w;
        As[lk + 4][lrow] = av1.x; As[lk + 5][lrow] = av1.y;
        As[lk + 6][lrow] = av1.z; As[lk + 7][lrow] = av1.w;
        Bs[lk + 0][lrow] = bv0.x; Bs[lk + 1][lrow] = bv0.y;
        Bs[lk + 2][lrow] = bv0.z; Bs[lk + 3][lrow] = bv0.w;
        Bs[lk + 4][lrow] = bv1.x; Bs[lk + 5][lrow] = bv1.y;
        Bs[lk + 6][lrow] = bv1.z; Bs[lk + 7][lrow] = bv1.w;
        __syncthreads();
#pragma unroll
        for (int k = 0; k < 16; k++) {
            float a[8], b[8];
            *(float4*)&a[0] = *(const float4*)&As[k][ty * 8];
            *(float4*)&a[4] = *(const float4*)&As[k][ty * 8 + 4];
            *(float4*)&b[0] = *(const float4*)&Bs[k][tx * 8];
            *(float4*)&b[4] = *(const float4*)&Bs[k][tx * 8 + 4];
#pragma unroll
            for (int i = 0; i < 8; i++)
#pragma unroll
                for (int j = 0; j < 8; j++)
                    acc[i][j] = fmaf(a[i], b[j], acc[i][j]);
        }
    }

    const int col = j0 + tx * 8;
    const int hh = col >> 8;
    const int oo = col & 255;
    float4 bw0 = *(const float4*)(bW + col);
    float4 bw1 = *(const float4*)(bW + col + 4);
#pragma unroll
    for (int i = 0; i < 8; i++) {
        int mrow = m0 + ty * 8 + i;
        int b = mrow >> 10, n = mrow & 1023;
        float* dst = g_Wh + (((size_t)(b * HH + hh) * NN + n) * FOUT + oo);
        float4 v0, v1;
        v0.x = acc[i][0] + bw0.x; v0.y = acc[i][1] + bw0.y;
        v0.z = acc[i][2] + bw0.z; v0.w = acc[i][3] + bw0.w;
        v1.x = acc[i][4] + bw1.x; v1.y = acc[i][5] + bw1.y;
        v1.z = acc[i][6] + bw1.z; v1.w = acc[i][7] + bw1.w;
        *(float4*)(dst)     = v0;
        *(float4*)(dst + 4) = v1;
    }
}

// ---------------------------------------------------------------------------
// Kernel 2: ei / ejb projections (one warp per row)
// ---------------------------------------------------------------------------
__global__ void __launch_bounds__(256) score_kernel(const float* __restrict__ a1,
                                                    const float* __restrict__ a2,
                                                    const float* __restrict__ bA)
{
    const int warp = threadIdx.x >> 5;
    const int lane = threadIdx.x & 31;
    const int row = blockIdx.x * 8 + warp;
    const int h = (row >> 10) & (HH - 1);

    const float4* wr = (const float4*)(g_Wh + (size_t)row * FOUT);
    const float4* p1 = (const float4*)(a1 + h * FOUT);
    const float4* p2 = (const float4*)(a2 + h * FOUT);

    float s1 = 0.f, s2 = 0.f;
#pragma unroll
    for (int u = 0; u < 2; u++) {
        float4 v = wr[lane + u * 32];
        float4 x = p1[lane + u * 32];
        float4 y = p2[lane + u * 32];
        s1 += v.x * x.x + v.y * x.y + v.z * x.z + v.w * x.w;
        s2 += v.x * y.x + v.y * y.y + v.z * y.z + v.w * y.w;
    }
#pragma unroll
    for (int off = 16; off > 0; off >>= 1) {
        s1 += __shfl_xor_sync(0xffffffffu, s1, off);
        s2 += __shfl_xor_sync(0xffffffffu, s2, off);
    }
    if (lane == 0) {
        g_ei[row] = s1;
        g_ejb[row] = s2 + bA[h];
    }
}

// ---------------------------------------------------------------------------
// Kernel 3: attention via mma.sync tf32 (m16n8k8) + factorized exp.
// Block = (b,h, 128-row i-tile). 512 threads = 16 warps (8 along M x 2 along N).
// P fragments computed directly in A-register layout; Wh tiles (32 j x 256 o)
// double-buffered in smem with k-permuted layout for LDS.128 B-frag loads.
// ---------------------------------------------------------------------------
#define BSTRIDE 36   // floats per Bs row (32 data + 4 pad), 16B-aligned

#define MMA_TF32(c, a0, a1, a2, a3, b0, b1) \
    asm volatile("mma.sync.aligned.m16n8k8.row.col.f32.tf32.tf32.f32 " \
        "{%0,%1,%2,%3}, {%4,%5,%6,%7}, {%8,%9}, {%0,%1,%2,%3};" \
        : "+f"((c)[0]), "+f"((c)[1]), "+f"((c)[2]), "+f"((c)[3]) \
        : "r"(a0), "r"(a1), "r"(a2), "r"(a3), "r"(b0), "r"(b1))

__device__ __forceinline__ uint32_t to_tf32(float x) {
    uint32_t u;
    asm("cvt.rna.tf32.f32 %0, %1;" : "=r"(u) : "f"(x));
    return u;
}

#define ATTN_SMEM ((2 * 256 * BSTRIDE + NN * 4 + 128) * 4)

__global__ void __launch_bounds__(512, 1) attn_mma_kernel(float* __restrict__ out)
{
    extern __shared__ float sm[];
    float4* equad = (float4*)(sm + 2 * 256 * BSTRIDE);  // (ej, e^ej, e^(0.2ej), 0) x 1024
    float*  linv  = sm + 2 * 256 * BSTRIDE + NN * 4;    // [128]

    const int tid  = threadIdx.x;
    const int lane = tid & 31;
    const int wid  = tid >> 5;
    const int mw   = wid & 7;
    const int nw   = wid >> 3;
    const int g    = lane >> 2;   // group id (row / n within frag)
    const int tg   = lane & 3;    // thread-in-group (k / col pair)
    const int bh   = blockIdx.x >> 3;
    const int it   = blockIdx.x & 7;

    // --- prologue: ej quads ---
    const float* ejg = g_ejb + (size_t)bh * NN;
#pragma unroll
    for (int q = 0; q < 2; q++) {
        int j = tid + q * 512;
        float e = ejg[j];
        equad[j] = make_float4(e, __expf(e), __expf(ALPHA * e), 0.f);
    }

    const int r1 = mw * 16 + g;   // warp rows r1, r1+8
    const float ei1 = g_ei[(size_t)bh * NN + it * 128 + r1];
    const float ei2 = g_ei[(size_t)bh * NN + it * 128 + r1 + 8];
    const float Ai1 = __expf(ei1), Bi1 = __expf(ALPHA * ei1);
    const float Ai2 = __expf(ei2), Bi2 = __expf(ALPHA * ei2);

    float acc[16][4];
#pragma unroll
    for (int f = 0; f < 16; f++)
#pragma unroll
        for (int c = 0; c < 4; c++) acc[f][c] = 0.f;

    // --- tile loader mapping: thread -> (o-block, j) ---
    const float* whbh = g_Wh + (size_t)bh * NN * FOUT;
    const int lo = (tid & 63) * 4;   // o base (floats), coalesced across warp
    const int lj = tid >> 6;         // j base 0..7 (j = lj + 8q)

    float4 st[4];
#pragma unroll
    for (int q = 0; q < 4; q++)
        st[q] = *(const float4*)(whbh + (size_t)(lj + 8 * q) * FOUT + lo);
#pragma unroll
    for (int q = 0; q < 4; q++) {
        int j = lj + 8 * q;
        int pj = ((j & 3) << 3) + (j >> 2);   // k-permuted column
        float* d = sm + pj;
        d[(lo + 0) * BSTRIDE] = st[q].x;
        d[(lo + 1) * BSTRIDE] = st[q].y;
        d[(lo + 2) * BSTRIDE] = st[q].z;
        d[(lo + 3) * BSTRIDE] = st[q].w;
    }
    __syncthreads();

    float lsum1 = 0.f, lsum2 = 0.f;

    for (int jt = 0; jt < 32; jt++) {
        const int cur = jt & 1;
        if (jt < 31) {
#pragma unroll
            for (int q = 0; q < 4; q++)
                st[q] = *(const float4*)(whbh +
                        (size_t)((jt + 1) * 32 + lj + 8 * q) * FOUT + lo);
        }

        // --- P fragments (A operand), factorized exp ---
        uint32_t aP[8][2];
#pragma unroll
        for (int t = 0; t < 8; t++) {
            float4 q4 = equad[jt * 32 + tg + 4 * t];
            float e1 = ei1 + q4.x;
            float p1 = (e1 > 0.f) ? Ai1 * q4.y : Bi1 * q4.z;
            uint32_t u1 = to_tf32(p1);
            float e2 = ei2 + q4.x;
            float p2 = (e2 > 0.f) ? Ai2 * q4.y : Bi2 * q4.z;
            uint32_t u2 = to_tf32(p2);
            aP[t][0] = u1; aP[t][1] = u2;
            if (nw == 0) {
                lsum1 += __uint_as_float(u1);
                lsum2 += __uint_as_float(u2);
            }
        }

        // --- MMAs: 16 n-frags x 4 k-steps ---
        const float* bsc = sm + cur * (256 * BSTRIDE);
#pragma unroll
        for (int f = 0; f < 16; f++) {
            const float* bp = bsc + (size_t)(nw * 128 + f * 8 + g) * BSTRIDE + tg * 8;
            uint4 b0 = *(const uint4*)bp;
            uint4 b1 = *(const uint4*)(bp + 4);
            MMA_TF32(acc[f], aP[0][0], aP[0][1], aP[1][0], aP[1][1], b0.x, b0.y);
            MMA_TF32(acc[f], aP[2][0], aP[2][1], aP[3][0], aP[3][1], b0.z, b0.w);
            MMA_TF32(acc[f], aP[4][0], aP[4][1], aP[5][0], aP[5][1], b1.x, b1.y);
            MMA_TF32(acc[f], aP[6][0], aP[6][1], aP[7][0], aP[7][1], b1.z, b1.w);
        }

        if (jt < 31) {
            float* bsn = sm + (cur ^ 1) * (256 * BSTRIDE);
#pragma unroll
            for (int q = 0; q < 4; q++) {
                int j = lj + 8 * q;
                int pj = ((j & 3) << 3) + (j >> 2);
                float* d = bsn + pj;
                d[(lo + 0) * BSTRIDE] = st[q].x;
                d[(lo + 1) * BSTRIDE] = st[q].y;
                d[(lo + 2) * BSTRIDE] = st[q].z;
                d[(lo + 3) * BSTRIDE] = st[q].w;
            }
        }
        __syncthreads();
    }

    // --- l reduction (rows covered by 4 lanes of nw==0 warps) ---
    if (nw == 0) {
        lsum1 += __shfl_xor_sync(0xffffffffu, lsum1, 1);
        lsum1 += __shfl_xor_sync(0xffffffffu, lsum1, 2);
        lsum2 += __shfl_xor_sync(0xffffffffu, lsum2, 1);
        lsum2 += __shfl_xor_sync(0xffffffffu, lsum2, 2);
        if (tg == 0) {
            linv[r1] = 1.f / lsum1;
            linv[r1 + 8] = 1.f / lsum2;
        }
    }
    __syncthreads();

    const float li1 = linv[r1];
    const float li2 = linv[r1 + 8];
    const int b = bh >> 3, h = bh & 7;
    float* o1 = out + (size_t)(b * NN + it * 128 + r1) * (HH * FOUT)
                    + h * FOUT + nw * 128;
    float* o2 = o1 + (size_t)8 * (HH * FOUT);

#pragma unroll
    for (int f = 0; f < 16; f++) {
        int oc = f * 8 + tg * 2;
        float x0 = fmaxf(acc[f][0] * li1, 0.f);
        float x1 = fmaxf(acc[f][1] * li1, 0.f);
        float x2 = fmaxf(acc[f][2] * li2, 0.f);
        float x3 = fmaxf(acc[f][3] * li2, 0.f);
        float2 v1, v2;
        v1.x = 1.f / (1.f + __expf(-x0));
        v1.y = 1.f / (1.f + __expf(-x1));
        v2.x = 1.f / (1.f + __expf(-x2));
        v2.y = 1.f / (1.f + __expf(-x3));
        *(float2*)(o1 + oc) = v1;
        *(float2*)(o2 + oc) = v2;
    }
}

// ---------------------------------------------------------------------------
extern "C" void kernel_launch(void* const* d_in, const int* in_sizes, int n_in,
                              void* d_out, int out_size)
{
    (void)in_sizes; (void)n_in; (void)out_size;
    const float* h_in = (const float*)d_in[0];
    const float* W    = (const float*)d_in[1];
    const float* bW   = (const float*)d_in[2];
    const float* a1   = (const float*)d_in[3];
    const float* a2   = (const float*)d_in[4];
    const float* bA   = (const float*)d_in[5];
    float* out = (float*)d_out;

    gemm1_kernel<<<dim3((BB * NN) / 128, (HH * FOUT) / 128), 256>>>(h_in, W, bW);
    score_kernel<<<(BB * HH * NN) / 8, 256>>>(a1, a2, bA);

    cudaFuncSetAttribute(attn_mma_kernel,
                         cudaFuncAttributeMaxDynamicSharedMemorySize, ATTN_SMEM);
    attn_mma_kernel<<<BB * HH * (NN / 128), 512, ATTN_SMEM>>>(out);
}

// round 4
// speedup vs baseline: 4.7329x; 1.4545x over previous
#include <cuda_runtime.h>
#include <stdint.h>
#include <math.h>

#define BB 16
#define NN 1024
#define FIN 256
#define FOUT 256
#define HH 8
#define ALPHA 0.2f

// Scratch (device globals; no allocations allowed)
__device__ float g_Wh[(size_t)BB * HH * NN * FOUT];   // [bh][n][o]
__device__ float g_ei[BB * HH * NN];                  // a1 . Wh_i
__device__ float g_ejb[BB * HH * NN];                 // a2 . Wh_j + bA[h]

// ---------------------------------------------------------------------------
// Kernel 1: Wh = h @ W^T + bW   (fp32 SIMT, proven)
// ---------------------------------------------------------------------------
__global__ void __launch_bounds__(256) gemm1_kernel(const float* __restrict__ A,
                                                    const float* __restrict__ Wf,
                                                    const float* __restrict__ bW)
{
    __shared__ float As[16][132];
    __shared__ float Bs[16][132];

    const int tid = threadIdx.x;
    const int tx = tid & 15;
    const int ty = tid >> 4;
    const int m0 = blockIdx.x * 128;
    const int j0 = blockIdx.y * 128;

    float acc[8][8];
#pragma unroll
    for (int i = 0; i < 8; i++)
#pragma unroll
        for (int j = 0; j < 8; j++) acc[i][j] = 0.f;

    const int lrow = tid >> 1;
    const int lk   = (tid & 1) * 8;

    const float* aptr = A  + (size_t)(m0 + lrow) * FIN + lk;
    const float* bptr = Wf + (size_t)(j0 + lrow) * FIN + lk;

    for (int k0 = 0; k0 < FIN; k0 += 16) {
        float4 av0 = *(const float4*)(aptr + k0);
        float4 av1 = *(const float4*)(aptr + k0 + 4);
        float4 bv0 = *(const float4*)(bptr + k0);
        float4 bv1 = *(const float4*)(bptr + k0 + 4);
        __syncthreads();
        As[lk + 0][lrow] = av0.x; As[lk + 1][lrow] = av0.y;
        As[lk + 2][lrow] = av0.z; As[lk + 3][lrow] = av0.w;
        As[lk + 4][lrow] = av1.x; As[lk + 5][lrow] = av1.y;
        As[lk + 6][lrow] = av1.z; As[lk + 7][lrow] = av1.w;
        Bs[lk + 0][lrow] = bv0.x; Bs[lk + 1][lrow] = bv0.y;
        Bs[lk + 2][lrow] = bv0.z; Bs[lk + 3][lrow] = bv0.w;
        Bs[lk + 4][lrow] = bv1.x; Bs[lk + 5][lrow] = bv1.y;
        Bs[lk + 6][lrow] = bv1.z; Bs[lk + 7][lrow] = bv1.w;
        __syncthreads();
#pragma unroll
        for (int k = 0; k < 16; k++) {
            float a[8], b[8];
            *(float4*)&a[0] = *(const float4*)&As[k][ty * 8];
            *(float4*)&a[4] = *(const float4*)&As[k][ty * 8 + 4];
            *(float4*)&b[0] = *(const float4*)&Bs[k][tx * 8];
            *(float4*)&b[4] = *(const float4*)&Bs[k][tx * 8 + 4];
#pragma unroll
            for (int i = 0; i < 8; i++)
#pragma unroll
                for (int j = 0; j < 8; j++)
                    acc[i][j] = fmaf(a[i], b[j], acc[i][j]);
        }
    }

    const int col = j0 + tx * 8;
    const int hh = col >> 8;
    const int oo = col & 255;
    float4 bw0 = *(const float4*)(bW + col);
    float4 bw1 = *(const float4*)(bW + col + 4);
#pragma unroll
    for (int i = 0; i < 8; i++) {
        int mrow = m0 + ty * 8 + i;
        int b = mrow >> 10, n = mrow & 1023;
        float* dst = g_Wh + (((size_t)(b * HH + hh) * NN + n) * FOUT + oo);
        float4 v0, v1;
        v0.x = acc[i][0] + bw0.x; v0.y = acc[i][1] + bw0.y;
        v0.z = acc[i][2] + bw0.z; v0.w = acc[i][3] + bw0.w;
        v1.x = acc[i][4] + bw1.x; v1.y = acc[i][5] + bw1.y;
        v1.z = acc[i][6] + bw1.z; v1.w = acc[i][7] + bw1.w;
        *(float4*)(dst)     = v0;
        *(float4*)(dst + 4) = v1;
    }
}

// ---------------------------------------------------------------------------
// Kernel 2: ei / ejb projections (one warp per row)
// ---------------------------------------------------------------------------
__global__ void __launch_bounds__(256) score_kernel(const float* __restrict__ a1,
                                                    const float* __restrict__ a2,
                                                    const float* __restrict__ bA)
{
    const int warp = threadIdx.x >> 5;
    const int lane = threadIdx.x & 31;
    const int row = blockIdx.x * 8 + warp;
    const int h = (row >> 10) & (HH - 1);

    const float4* wr = (const float4*)(g_Wh + (size_t)row * FOUT);
    const float4* p1 = (const float4*)(a1 + h * FOUT);
    const float4* p2 = (const float4*)(a2 + h * FOUT);

    float s1 = 0.f, s2 = 0.f;
#pragma unroll
    for (int u = 0; u < 2; u++) {
        float4 v = wr[lane + u * 32];
        float4 x = p1[lane + u * 32];
        float4 y = p2[lane + u * 32];
        s1 += v.x * x.x + v.y * x.y + v.z * x.z + v.w * x.w;
        s2 += v.x * y.x + v.y * y.y + v.z * y.z + v.w * y.w;
    }
#pragma unroll
    for (int off = 16; off > 0; off >>= 1) {
        s1 += __shfl_xor_sync(0xffffffffu, s1, off);
        s2 += __shfl_xor_sync(0xffffffffu, s2, off);
    }
    if (lane == 0) {
        g_ei[row] = s1;
        g_ejb[row] = s2 + bA[h];
    }
}

// ---------------------------------------------------------------------------
// Kernel 3: attention via mma.sync tf32 (m16n8k8) + factorized exp.
// B tile in smem: [o(256)][32 floats] with chunk-XOR swizzle:
//   chunk'(o, c) = c ^ (o & 7) ^ ((o >> 2) & 7)
// (c = unswizzled 16B chunk index of the k-permuted column pj = (j&3)*8 + j>>2)
// Loader: register 4x4 transpose -> 4 conflict-free STS.128 per thread.
// Fragment loads: 2 conflict-free LDS.128 per (f) per thread (same data order
// as R3, so MMA inputs are bit-identical).
// ---------------------------------------------------------------------------
#define MMA_TF32(c, a0, a1, a2, a3, b0, b1) \
    asm volatile("mma.sync.aligned.m16n8k8.row.col.f32.tf32.tf32.f32 " \
        "{%0,%1,%2,%3}, {%4,%5,%6,%7}, {%8,%9}, {%0,%1,%2,%3};" \
        : "+f"((c)[0]), "+f"((c)[1]), "+f"((c)[2]), "+f"((c)[3]) \
        : "r"(a0), "r"(a1), "r"(a2), "r"(a3), "r"(b0), "r"(b1))

__device__ __forceinline__ uint32_t to_tf32(float x) {
    uint32_t u;
    asm("cvt.rna.tf32.f32 %0, %1;" : "=r"(u) : "f"(x));
    return u;
}

#define BUF_FLOATS (256 * 32)          // one B tile: 256 o-rows x 32 floats
#define ATTN_SMEM ((2 * BUF_FLOATS + NN * 4 + 128) * 4)

__global__ void __launch_bounds__(512, 1) attn_mma_kernel(float* __restrict__ out)
{
    extern __shared__ float sm[];
    float4* equad = (float4*)(sm + 2 * BUF_FLOATS);  // (ej, e^ej, e^(.2ej), 0) x1024
    float*  linv  = sm + 2 * BUF_FLOATS + NN * 4;    // [128]

    const int tid  = threadIdx.x;
    const int lane = tid & 31;
    const int wid  = tid >> 5;
    const int mw   = wid & 7;
    const int nw   = wid >> 3;
    const int g    = lane >> 2;
    const int tg   = lane & 3;
    const int bh   = blockIdx.x >> 3;
    const int it   = blockIdx.x & 7;

    // --- prologue: ej quads ---
    const float* ejg = g_ejb + (size_t)bh * NN;
#pragma unroll
    for (int q = 0; q < 2; q++) {
        int j = tid + q * 512;
        float e = ejg[j];
        equad[j] = make_float4(e, __expf(e), __expf(ALPHA * e), 0.f);
    }

    const int r1 = mw * 16 + g;
    const float ei1 = g_ei[(size_t)bh * NN + it * 128 + r1];
    const float ei2 = g_ei[(size_t)bh * NN + it * 128 + r1 + 8];
    const float Ai1 = __expf(ei1), Bi1 = __expf(ALPHA * ei1);
    const float Ai2 = __expf(ei2), Bi2 = __expf(ALPHA * ei2);

    float acc[16][4];
#pragma unroll
    for (int f = 0; f < 16; f++)
#pragma unroll
        for (int c = 0; c < 4; c++) acc[f][c] = 0.f;

    // --- loader mapping: thread -> 4x4 (j, o) block ---
    const float* whbh = g_Wh + (size_t)bh * NN * FOUT;
    const int jg  = tid >> 6;          // 0..7
    const int tgp = jg & 3;
    const int ch  = jg >> 2;           // 0/1
    const int jb  = tgp + 16 * ch;     // j = jb + 4q, q = 0..3
    const int cc  = tgp * 2 + ch;      // unswizzled chunk of this j-quad
    const int o0  = (tid & 63) * 4;    // o base

    float4 st[4];
#pragma unroll
    for (int q = 0; q < 4; q++)
        st[q] = *(const float4*)(whbh + (size_t)(jb + 4 * q) * FOUT + o0);

    // transpose + swizzled conflict-free stores into buffer 0
    {
        float* buf = sm;
#pragma unroll
        for (int k = 0; k < 4; k++) {
            int o = o0 + k;
            int cp = cc ^ (o & 7) ^ ((o >> 2) & 7);
            float4 V;
            V.x = ((const float*)&st[0])[k];
            V.y = ((const float*)&st[1])[k];
            V.z = ((const float*)&st[2])[k];
            V.w = ((const float*)&st[3])[k];
            *(float4*)(buf + o * 32 + cp * 4) = V;
        }
    }
    __syncthreads();

    float lsum1 = 0.f, lsum2 = 0.f;

    for (int jt = 0; jt < 32; jt++) {
        const int cur = jt & 1;
        if (jt < 31) {
#pragma unroll
            for (int q = 0; q < 4; q++)
                st[q] = *(const float4*)(whbh +
                        (size_t)((jt + 1) * 32 + jb + 4 * q) * FOUT + o0);
        }

        // --- P fragments (A operand), factorized exp ---
        uint32_t aP[8][2];
#pragma unroll
        for (int t = 0; t < 8; t++) {
            float4 q4 = equad[jt * 32 + tg + 4 * t];
            float e1 = ei1 + q4.x;
            float p1 = (e1 > 0.f) ? Ai1 * q4.y : Bi1 * q4.z;
            uint32_t u1 = to_tf32(p1);
            float e2 = ei2 + q4.x;
            float p2 = (e2 > 0.f) ? Ai2 * q4.y : Bi2 * q4.z;
            uint32_t u2 = to_tf32(p2);
            aP[t][0] = u1; aP[t][1] = u2;
            if (nw == 0) {
                lsum1 += __uint_as_float(u1);
                lsum2 += __uint_as_float(u2);
            }
        }

        // --- MMAs: 16 n-frags x 4 k-steps, swizzled conflict-free B loads ---
        const float* bsc = sm + cur * BUF_FLOATS;
#pragma unroll
        for (int f = 0; f < 16; f++) {
            const int orow = nw * 128 + f * 8 + g;
            const int sw = (orow & 7) ^ ((orow >> 2) & 7);
            const float* bp = bsc + orow * 32;
            uint4 b0 = *(const uint4*)(bp + (((2 * tg) ^ sw) * 4));
            uint4 b1 = *(const uint4*)(bp + (((2 * tg + 1) ^ sw) * 4));
            MMA_TF32(acc[f], aP[0][0], aP[0][1], aP[1][0], aP[1][1], b0.x, b0.y);
            MMA_TF32(acc[f], aP[2][0], aP[2][1], aP[3][0], aP[3][1], b0.z, b0.w);
            MMA_TF32(acc[f], aP[4][0], aP[4][1], aP[5][0], aP[5][1], b1.x, b1.y);
            MMA_TF32(acc[f], aP[6][0], aP[6][1], aP[7][0], aP[7][1], b1.z, b1.w);
        }

        if (jt < 31) {
            float* bsn = sm + (cur ^ 1) * BUF_FLOATS;
#pragma unroll
            for (int k = 0; k < 4; k++) {
                int o = o0 + k;
                int cp = cc ^ (o & 7) ^ ((o >> 2) & 7);
                float4 V;
                V.x = ((const float*)&st[0])[k];
                V.y = ((const float*)&st[1])[k];
                V.z = ((const float*)&st[2])[k];
                V.w = ((const float*)&st[3])[k];
                *(float4*)(bsn + o * 32 + cp * 4) = V;
            }
        }
        __syncthreads();
    }

    // --- l reduction ---
    if (nw == 0) {
        lsum1 += __shfl_xor_sync(0xffffffffu, lsum1, 1);
        lsum1 += __shfl_xor_sync(0xffffffffu, lsum1, 2);
        lsum2 += __shfl_xor_sync(0xffffffffu, lsum2, 1);
        lsum2 += __shfl_xor_sync(0xffffffffu, lsum2, 2);
        if (tg == 0) {
            linv[r1] = 1.f / lsum1;
            linv[r1 + 8] = 1.f / lsum2;
        }
    }
    __syncthreads();

    const float li1 = linv[r1];
    const float li2 = linv[r1 + 8];
    const int b = bh >> 3, h = bh & 7;
    float* o1 = out + (size_t)(b * NN + it * 128 + r1) * (HH * FOUT)
                    + h * FOUT + nw * 128;
    float* o2 = o1 + (size_t)8 * (HH * FOUT);

#pragma unroll
    for (int f = 0; f < 16; f++) {
        int oc = f * 8 + tg * 2;
        float x0 = fmaxf(acc[f][0] * li1, 0.f);
        float x1 = fmaxf(acc[f][1] * li1, 0.f);
        float x2 = fmaxf(acc[f][2] * li2, 0.f);
        float x3 = fmaxf(acc[f][3] * li2, 0.f);
        float2 v1, v2;
        v1.x = 1.f / (1.f + __expf(-x0));
        v1.y = 1.f / (1.f + __expf(-x1));
        v2.x = 1.f / (1.f + __expf(-x2));
        v2.y = 1.f / (1.f + __expf(-x3));
        *(float2*)(o1 + oc) = v1;
        *(float2*)(o2 + oc) = v2;
    }
}

// ---------------------------------------------------------------------------
extern "C" void kernel_launch(void* const* d_in, const int* in_sizes, int n_in,
                              void* d_out, int out_size)
{
    (void)in_sizes; (void)n_in; (void)out_size;
    const float* h_in = (const float*)d_in[0];
    const float* W    = (const float*)d_in[1];
    const float* bW   = (const float*)d_in[2];
    const float* a1   = (const float*)d_in[3];
    const float* a2   = (const float*)d_in[4];
    const float* bA   = (const float*)d_in[5];
    float* out = (float*)d_out;

    gemm1_kernel<<<dim3((BB * NN) / 128, (HH * FOUT) / 128), 256>>>(h_in, W, bW);
    score_kernel<<<(BB * HH * NN) / 8, 256>>>(a1, a2, bA);

    cudaFuncSetAttribute(attn_mma_kernel,
                         cudaFuncAttributeMaxDynamicSharedMemorySize, ATTN_SMEM);
    attn_mma_kernel<<<BB * HH * (NN / 128), 512, ATTN_SMEM>>>(out);
}

// round 5
// speedup vs baseline: 5.0065x; 1.0578x over previous
#include <cuda_runtime.h>
#include <stdint.h>
#include <math.h>

#define BB 16
#define NN 1024
#define FIN 256
#define FOUT 256
#define HH 8
#define ALPHA 0.2f

// Scratch (device globals; no allocations allowed)
__device__ float g_Wh[(size_t)BB * HH * NN * FOUT];   // [bh][n][o]
__device__ float g_ei[BB * HH * NN];                  // a1 . Wh_i
__device__ float g_ejb[BB * HH * NN];                 // a2 . Wh_j + bA[h]

#define MMA_TF32(c, a0, a1, a2, a3, b0, b1) \
    asm volatile("mma.sync.aligned.m16n8k8.row.col.f32.tf32.tf32.f32 " \
        "{%0,%1,%2,%3}, {%4,%5,%6,%7}, {%8,%9}, {%0,%1,%2,%3};" \
        : "+f"((c)[0]), "+f"((c)[1]), "+f"((c)[2]), "+f"((c)[3]) \
        : "r"(a0), "r"(a1), "r"(a2), "r"(a3), "r"(b0), "r"(b1))

__device__ __forceinline__ uint32_t to_tf32(float x) {
    uint32_t u;
    asm("cvt.rna.tf32.f32 %0, %1;" : "=r"(u) : "f"(x));
    return u;
}

// ---------------------------------------------------------------------------
// Kernel 1: Wh = h @ W^T + bW via 3xTF32 mma.sync (near-fp32 accuracy).
// CTA: 128 rows (m) x 128 cols (j), K=256 in 8 tiles of 32.
// 256 threads = 8 warps: mw = wid&1 (M 64), nw = wid>>1 (N 32).
// smem: transposed big/small planes [k(32)][136 pad] -> bank = (8k+m)%32,
// conflict-free for transposed stores and all fragment loads.
// ---------------------------------------------------------------------------
#define G1_PAD 136
#define G1_PLANE (32 * G1_PAD)              // floats per plane
#define G1_SMEM (4 * G1_PLANE * 4)          // bytes

__global__ void __launch_bounds__(256, 2) gemm1_tc_kernel(const float* __restrict__ A,
                                                          const float* __restrict__ Wf,
                                                          const float* __restrict__ bWp)
{
    extern __shared__ float gs[];
    float* Abig = gs;
    float* Asml = gs + G1_PLANE;
    float* Bbig = gs + 2 * G1_PLANE;
    float* Bsml = gs + 3 * G1_PLANE;

    const int tid  = threadIdx.x;
    const int lane = tid & 31;
    const int wid  = tid >> 5;
    const int mw   = wid & 1;
    const int nw   = wid >> 1;
    const int g    = lane >> 2;
    const int tg   = lane & 3;
    const int m0   = blockIdx.x * 128;
    const int j0   = blockIdx.y * 128;

    const int lm = tid & 127;      // loader row (m for A, local j for B)
    const int kh = tid >> 7;       // k half: 0 or 1 (16 k each)

    float acc[4][4][4];            // [mi][f][c]
#pragma unroll
    for (int mi = 0; mi < 4; mi++)
#pragma unroll
        for (int f = 0; f < 4; f++)
#pragma unroll
            for (int c = 0; c < 4; c++) acc[mi][f][c] = 0.f;

    const float* apr = A  + (size_t)(m0 + lm) * FIN + kh * 16;
    const float* bpr = Wf + (size_t)(j0 + lm) * FIN + kh * 16;

    for (int kt = 0; kt < 8; kt++) {
        __syncthreads();
        // --- stage + split A and B tiles (transposed, conflict-free STS) ---
#pragma unroll
        for (int q = 0; q < 4; q++) {
            float4 va = *(const float4*)(apr + kt * 32 + q * 4);
            float4 vb = *(const float4*)(bpr + kt * 32 + q * 4);
            float aa[4] = {va.x, va.y, va.z, va.w};
            float bb[4] = {vb.x, vb.y, vb.z, vb.w};
#pragma unroll
            for (int e = 0; e < 4; e++) {
                int k = kh * 16 + q * 4 + e;
                float abf = __uint_as_float(to_tf32(aa[e]));
                Abig[k * G1_PAD + lm] = abf;
                Asml[k * G1_PAD + lm] = __uint_as_float(to_tf32(aa[e] - abf));
                float bbf = __uint_as_float(to_tf32(bb[e]));
                Bbig[k * G1_PAD + lm] = bbf;
                Bsml[k * G1_PAD + lm] = __uint_as_float(to_tf32(bb[e] - bbf));
            }
        }
        __syncthreads();

        // --- MMA phase: 4 k8-steps ---
#pragma unroll
        for (int ks = 0; ks < 4; ks++) {
            const int kk = ks * 8;
            uint32_t ab[4][4], as[4][4];
#pragma unroll
            for (int mi = 0; mi < 4; mi++) {
                int r0 = mw * 64 + mi * 16 + g;
                ab[mi][0] = __float_as_uint(Abig[(kk + tg) * G1_PAD + r0]);
                ab[mi][1] = __float_as_uint(Abig[(kk + tg) * G1_PAD + r0 + 8]);
                ab[mi][2] = __float_as_uint(Abig[(kk + tg + 4) * G1_PAD + r0]);
                ab[mi][3] = __float_as_uint(Abig[(kk + tg + 4) * G1_PAD + r0 + 8]);
                as[mi][0] = __float_as_uint(Asml[(kk + tg) * G1_PAD + r0]);
                as[mi][1] = __float_as_uint(Asml[(kk + tg) * G1_PAD + r0 + 8]);
                as[mi][2] = __float_as_uint(Asml[(kk + tg + 4) * G1_PAD + r0]);
                as[mi][3] = __float_as_uint(Asml[(kk + tg + 4) * G1_PAD + r0 + 8]);
            }
#pragma unroll
            for (int f = 0; f < 4; f++) {
                int n = nw * 32 + f * 8 + g;
                uint32_t bb0 = __float_as_uint(Bbig[(kk + tg) * G1_PAD + n]);
                uint32_t bb1 = __float_as_uint(Bbig[(kk + tg + 4) * G1_PAD + n]);
                uint32_t bs0 = __float_as_uint(Bsml[(kk + tg) * G1_PAD + n]);
                uint32_t bs1 = __float_as_uint(Bsml[(kk + tg + 4) * G1_PAD + n]);
#pragma unroll
                for (int mi = 0; mi < 4; mi++) {
                    MMA_TF32(acc[mi][f], ab[mi][0], ab[mi][1], ab[mi][2], ab[mi][3], bb0, bb1);
                    MMA_TF32(acc[mi][f], as[mi][0], as[mi][1], as[mi][2], as[mi][3], bb0, bb1);
                    MMA_TF32(acc[mi][f], ab[mi][0], ab[mi][1], ab[mi][2], ab[mi][3], bs0, bs1);
                }
            }
        }
    }

    // --- epilogue: + bias, scatter to g_Wh[b][h][n][o] ---
#pragma unroll
    for (int f = 0; f < 4; f++) {
        const int c = j0 + nw * 32 + f * 8 + tg * 2;
        const float bw0 = bWp[c];
        const float bw1 = bWp[c + 1];
        const int h = c >> 8;
        const int o = c & 255;
#pragma unroll
        for (int mi = 0; mi < 4; mi++) {
            int r0 = m0 + mw * 64 + mi * 16 + g;
            int b0i = r0 >> 10, n0i = r0 & 1023;
            int r1 = r0 + 8;
            int b1i = r1 >> 10, n1i = r1 & 1023;
            float2 v0, v1;
            v0.x = acc[mi][f][0] + bw0; v0.y = acc[mi][f][1] + bw1;
            v1.x = acc[mi][f][2] + bw0; v1.y = acc[mi][f][3] + bw1;
            *(float2*)(g_Wh + (((size_t)(b0i * HH + h) * NN + n0i) * FOUT + o)) = v0;
            *(float2*)(g_Wh + (((size_t)(b1i * HH + h) * NN + n1i) * FOUT + o)) = v1;
        }
    }
}

// ---------------------------------------------------------------------------
// Kernel 2: ei / ejb projections (one warp per row)
// ---------------------------------------------------------------------------
__global__ void __launch_bounds__(256) score_kernel(const float* __restrict__ a1,
                                                    const float* __restrict__ a2,
                                                    const float* __restrict__ bA)
{
    const int warp = threadIdx.x >> 5;
    const int lane = threadIdx.x & 31;
    const int row = blockIdx.x * 8 + warp;
    const int h = (row >> 10) & (HH - 1);

    const float4* wr = (const float4*)(g_Wh + (size_t)row * FOUT);
    const float4* p1 = (const float4*)(a1 + h * FOUT);
    const float4* p2 = (const float4*)(a2 + h * FOUT);

    float s1 = 0.f, s2 = 0.f;
#pragma unroll
    for (int u = 0; u < 2; u++) {
        float4 v = wr[lane + u * 32];
        float4 x = p1[lane + u * 32];
        float4 y = p2[lane + u * 32];
        s1 += v.x * x.x + v.y * x.y + v.z * x.z + v.w * x.w;
        s2 += v.x * y.x + v.y * y.y + v.z * y.z + v.w * y.w;
    }
#pragma unroll
    for (int off = 16; off > 0; off >>= 1) {
        s1 += __shfl_xor_sync(0xffffffffu, s1, off);
        s2 += __shfl_xor_sync(0xffffffffu, s2, off);
    }
    if (lane == 0) {
        g_ei[row] = s1;
        g_ejb[row] = s2 + bA[h];
    }
}

// ---------------------------------------------------------------------------
// Kernel 3: attention via mma.sync tf32 (m16n8k8) + factorized exp.
// (unchanged from R4 — validated, conflict-free swizzled B pipeline)
// ---------------------------------------------------------------------------
#define BUF_FLOATS (256 * 32)
#define ATTN_SMEM ((2 * BUF_FLOATS + NN * 4 + 128) * 4)

__global__ void __launch_bounds__(512, 1) attn_mma_kernel(float* __restrict__ out)
{
    extern __shared__ float sm[];
    float4* equad = (float4*)(sm + 2 * BUF_FLOATS);
    float*  linv  = sm + 2 * BUF_FLOATS + NN * 4;

    const int tid  = threadIdx.x;
    const int lane = tid & 31;
    const int wid  = tid >> 5;
    const int mw   = wid & 7;
    const int nw   = wid >> 3;
    const int g    = lane >> 2;
    const int tg   = lane & 3;
    const int bh   = blockIdx.x >> 3;
    const int it   = blockIdx.x & 7;

    const float* ejg = g_ejb + (size_t)bh * NN;
#pragma unroll
    for (int q = 0; q < 2; q++) {
        int j = tid + q * 512;
        float e = ejg[j];
        equad[j] = make_float4(e, __expf(e), __expf(ALPHA * e), 0.f);
    }

    const int r1 = mw * 16 + g;
    const float ei1 = g_ei[(size_t)bh * NN + it * 128 + r1];
    const float ei2 = g_ei[(size_t)bh * NN + it * 128 + r1 + 8];
    const float Ai1 = __expf(ei1), Bi1 = __expf(ALPHA * ei1);
    const float Ai2 = __expf(ei2), Bi2 = __expf(ALPHA * ei2);

    float acc[16][4];
#pragma unroll
    for (int f = 0; f < 16; f++)
#pragma unroll
        for (int c = 0; c < 4; c++) acc[f][c] = 0.f;

    const float* whbh = g_Wh + (size_t)bh * NN * FOUT;
    const int jg  = tid >> 6;
    const int tgp = jg & 3;
    const int ch  = jg >> 2;
    const int jb  = tgp + 16 * ch;
    const int cc  = tgp * 2 + ch;
    const int o0  = (tid & 63) * 4;

    float4 st[4];
#pragma unroll
    for (int q = 0; q < 4; q++)
        st[q] = *(const float4*)(whbh + (size_t)(jb + 4 * q) * FOUT + o0);

    {
        float* buf = sm;
#pragma unroll
        for (int k = 0; k < 4; k++) {
            int o = o0 + k;
            int cp = cc ^ (o & 7) ^ ((o >> 2) & 7);
            float4 V;
            V.x = ((const float*)&st[0])[k];
            V.y = ((const float*)&st[1])[k];
            V.z = ((const float*)&st[2])[k];
            V.w = ((const float*)&st[3])[k];
            *(float4*)(buf + o * 32 + cp * 4) = V;
        }
    }
    __syncthreads();

    float lsum1 = 0.f, lsum2 = 0.f;

    for (int jt = 0; jt < 32; jt++) {
        const int cur = jt & 1;
        if (jt < 31) {
#pragma unroll
            for (int q = 0; q < 4; q++)
                st[q] = *(const float4*)(whbh +
                        (size_t)((jt + 1) * 32 + jb + 4 * q) * FOUT + o0);
        }

        uint32_t aP[8][2];
#pragma unroll
        for (int t = 0; t < 8; t++) {
            float4 q4 = equad[jt * 32 + tg + 4 * t];
            float e1 = ei1 + q4.x;
            float p1 = (e1 > 0.f) ? Ai1 * q4.y : Bi1 * q4.z;
            uint32_t u1 = to_tf32(p1);
            float e2 = ei2 + q4.x;
            float p2 = (e2 > 0.f) ? Ai2 * q4.y : Bi2 * q4.z;
            uint32_t u2 = to_tf32(p2);
            aP[t][0] = u1; aP[t][1] = u2;
            if (nw == 0) {
                lsum1 += __uint_as_float(u1);
                lsum2 += __uint_as_float(u2);
            }
        }

        const float* bsc = sm + cur * BUF_FLOATS;
#pragma unroll
        for (int f = 0; f < 16; f++) {
            const int orow = nw * 128 + f * 8 + g;
            const int sw = (orow & 7) ^ ((orow >> 2) & 7);
            const float* bp = bsc + orow * 32;
            uint4 b0 = *(const uint4*)(bp + (((2 * tg) ^ sw) * 4));
            uint4 b1 = *(const uint4*)(bp + (((2 * tg + 1) ^ sw) * 4));
            MMA_TF32(acc[f], aP[0][0], aP[0][1], aP[1][0], aP[1][1], b0.x, b0.y);
            MMA_TF32(acc[f], aP[2][0], aP[2][1], aP[3][0], aP[3][1], b0.z, b0.w);
            MMA_TF32(acc[f], aP[4][0], aP[4][1], aP[5][0], aP[5][1], b1.x, b1.y);
            MMA_TF32(acc[f], aP[6][0], aP[6][1], aP[7][0], aP[7][1], b1.z, b1.w);
        }

        if (jt < 31) {
            float* bsn = sm + (cur ^ 1) * BUF_FLOATS;
#pragma unroll
            for (int k = 0; k < 4; k++) {
                int o = o0 + k;
                int cp = cc ^ (o & 7) ^ ((o >> 2) & 7);
                float4 V;
                V.x = ((const float*)&st[0])[k];
                V.y = ((const float*)&st[1])[k];
                V.z = ((const float*)&st[2])[k];
                V.w = ((const float*)&st[3])[k];
                *(float4*)(bsn + o * 32 + cp * 4) = V;
            }
        }
        __syncthreads();
    }

    if (nw == 0) {
        lsum1 += __shfl_xor_sync(0xffffffffu, lsum1, 1);
        lsum1 += __shfl_xor_sync(0xffffffffu, lsum1, 2);
        lsum2 += __shfl_xor_sync(0xffffffffu, lsum2, 1);
        lsum2 += __shfl_xor_sync(0xffffffffu, lsum2, 2);
        if (tg == 0) {
            linv[r1] = 1.f / lsum1;
            linv[r1 + 8] = 1.f / lsum2;
        }
    }
    __syncthreads();

    const float li1 = linv[r1];
    const float li2 = linv[r1 + 8];
    const int b = bh >> 3, h = bh & 7;
    float* o1 = out + (size_t)(b * NN + it * 128 + r1) * (HH * FOUT)
                    + h * FOUT + nw * 128;
    float* o2 = o1 + (size_t)8 * (HH * FOUT);

#pragma unroll
    for (int f = 0; f < 16; f++) {
        int oc = f * 8 + tg * 2;
        float x0 = fmaxf(acc[f][0] * li1, 0.f);
        float x1 = fmaxf(acc[f][1] * li1, 0.f);
        float x2 = fmaxf(acc[f][2] * li2, 0.f);
        float x3 = fmaxf(acc[f][3] * li2, 0.f);
        float2 v1, v2;
        v1.x = 1.f / (1.f + __expf(-x0));
        v1.y = 1.f / (1.f + __expf(-x1));
        v2.x = 1.f / (1.f + __expf(-x2));
        v2.y = 1.f / (1.f + __expf(-x3));
        *(float2*)(o1 + oc) = v1;
        *(float2*)(o2 + oc) = v2;
    }
}

// ---------------------------------------------------------------------------
extern "C" void kernel_launch(void* const* d_in, const int* in_sizes, int n_in,
                              void* d_out, int out_size)
{
    (void)in_sizes; (void)n_in; (void)out_size;
    const float* h_in = (const float*)d_in[0];
    const float* W    = (const float*)d_in[1];
    const float* bW   = (const float*)d_in[2];
    const float* a1   = (const float*)d_in[3];
    const float* a2   = (const float*)d_in[4];
    const float* bA   = (const float*)d_in[5];
    float* out = (float*)d_out;

    cudaFuncSetAttribute(gemm1_tc_kernel,
                         cudaFuncAttributeMaxDynamicSharedMemorySize, G1_SMEM);
    gemm1_tc_kernel<<<dim3(128, 16), 256, G1_SMEM>>>(h_in, W, bW);

    score_kernel<<<(BB * HH * NN) / 8, 256>>>(a1, a2, bA);

    cudaFuncSetAttribute(attn_mma_kernel,
                         cudaFuncAttributeMaxDynamicSharedMemorySize, ATTN_SMEM);
    attn_mma_kernel<<<BB * HH * (NN / 128), 512, ATTN_SMEM>>>(out);
}

// round 6
// speedup vs baseline: 5.4199x; 1.0826x over previous
#include <cuda_runtime.h>
#include <stdint.h>
#include <math.h>

#define BB 16
#define NN 1024
#define FIN 256
#define FOUT 256
#define HH 8
#define ALPHA 0.2f

// Scratch (device globals; no allocations allowed)
__device__ float g_Wh[(size_t)BB * HH * NN * FOUT];   // [bh][n][o]
__device__ float g_ei[BB * HH * NN];                  // a1 . Wh_i
__device__ float g_ejb[BB * HH * NN];                 // a2 . Wh_j + bA[h]

#define MMA_TF32(c, a0, a1, a2, a3, b0, b1) \
    asm volatile("mma.sync.aligned.m16n8k8.row.col.f32.tf32.tf32.f32 " \
        "{%0,%1,%2,%3}, {%4,%5,%6,%7}, {%8,%9}, {%0,%1,%2,%3};" \
        : "+f"((c)[0]), "+f"((c)[1]), "+f"((c)[2]), "+f"((c)[3]) \
        : "r"(a0), "r"(a1), "r"(a2), "r"(a3), "r"(b0), "r"(b1))

#define MMA_BF16(c, a0, a1, a2, a3, b0, b1) \
    asm volatile("mma.sync.aligned.m16n8k16.row.col.f32.bf16.bf16.f32 " \
        "{%0,%1,%2,%3}, {%4,%5,%6,%7}, {%8,%9}, {%0,%1,%2,%3};" \
        : "+f"((c)[0]), "+f"((c)[1]), "+f"((c)[2]), "+f"((c)[3]) \
        : "r"(a0), "r"(a1), "r"(a2), "r"(a3), "r"(b0), "r"(b1))

// pack two fp32 -> bf16x2, lo = first arg
#define PACK_BF16X2(r, lo, hi) \
    asm("cvt.rn.bf16x2.f32 %0, %1, %2;" : "=r"(r) : "f"(hi), "f"(lo))

__device__ __forceinline__ uint32_t to_tf32(float x) {
    uint32_t u;
    asm("cvt.rna.tf32.f32 %0, %1;" : "=r"(u) : "f"(x));
    return u;
}
__device__ __forceinline__ uint32_t smem_u32(const void* p) {
    uint32_t a;
    asm("{ .reg .u64 t; cvta.to.shared.u64 t, %1; cvt.u32.u64 %0, t; }"
        : "=r"(a) : "l"(p));
    return a;
}
__device__ __forceinline__ void ldsm_x4_t(uint32_t& r0, uint32_t& r1,
                                          uint32_t& r2, uint32_t& r3, uint32_t addr) {
    asm volatile("ldmatrix.sync.aligned.m8n8.x4.trans.shared.b16 "
                 "{%0,%1,%2,%3}, [%4];"
                 : "=r"(r0), "=r"(r1), "=r"(r2), "=r"(r3) : "r"(addr));
}

// ---------------------------------------------------------------------------
// Kernel 1: Wh = h @ W^T + bW via 3xTF32 mma.sync (unchanged from R5, 352us)
// ---------------------------------------------------------------------------
#define G1_PAD 136
#define G1_PLANE (32 * G1_PAD)
#define G1_SMEM (4 * G1_PLANE * 4)

__global__ void __launch_bounds__(256, 2) gemm1_tc_kernel(const float* __restrict__ A,
                                                          const float* __restrict__ Wf,
                                                          const float* __restrict__ bWp)
{
    extern __shared__ float gs[];
    float* Abig = gs;
    float* Asml = gs + G1_PLANE;
    float* Bbig = gs + 2 * G1_PLANE;
    float* Bsml = gs + 3 * G1_PLANE;

    const int tid  = threadIdx.x;
    const int lane = tid & 31;
    const int wid  = tid >> 5;
    const int mw   = wid & 1;
    const int nw   = wid >> 1;
    const int g    = lane >> 2;
    const int tg   = lane & 3;
    const int m0   = blockIdx.x * 128;
    const int j0   = blockIdx.y * 128;

    const int lm = tid & 127;
    const int kh = tid >> 7;

    float acc[4][4][4];
#pragma unroll
    for (int mi = 0; mi < 4; mi++)
#pragma unroll
        for (int f = 0; f < 4; f++)
#pragma unroll
            for (int c = 0; c < 4; c++) acc[mi][f][c] = 0.f;

    const float* apr = A  + (size_t)(m0 + lm) * FIN + kh * 16;
    const float* bpr = Wf + (size_t)(j0 + lm) * FIN + kh * 16;

    for (int kt = 0; kt < 8; kt++) {
        __syncthreads();
#pragma unroll
        for (int q = 0; q < 4; q++) {
            float4 va = *(const float4*)(apr + kt * 32 + q * 4);
            float4 vb = *(const float4*)(bpr + kt * 32 + q * 4);
            float aa[4] = {va.x, va.y, va.z, va.w};
            float bb[4] = {vb.x, vb.y, vb.z, vb.w};
#pragma unroll
            for (int e = 0; e < 4; e++) {
                int k = kh * 16 + q * 4 + e;
                float abf = __uint_as_float(to_tf32(aa[e]));
                Abig[k * G1_PAD + lm] = abf;
                Asml[k * G1_PAD + lm] = __uint_as_float(to_tf32(aa[e] - abf));
                float bbf = __uint_as_float(to_tf32(bb[e]));
                Bbig[k * G1_PAD + lm] = bbf;
                Bsml[k * G1_PAD + lm] = __uint_as_float(to_tf32(bb[e] - bbf));
            }
        }
        __syncthreads();

#pragma unroll
        for (int ks = 0; ks < 4; ks++) {
            const int kk = ks * 8;
            uint32_t ab[4][4], as[4][4];
#pragma unroll
            for (int mi = 0; mi < 4; mi++) {
                int r0 = mw * 64 + mi * 16 + g;
                ab[mi][0] = __float_as_uint(Abig[(kk + tg) * G1_PAD + r0]);
                ab[mi][1] = __float_as_uint(Abig[(kk + tg) * G1_PAD + r0 + 8]);
                ab[mi][2] = __float_as_uint(Abig[(kk + tg + 4) * G1_PAD + r0]);
                ab[mi][3] = __float_as_uint(Abig[(kk + tg + 4) * G1_PAD + r0 + 8]);
                as[mi][0] = __float_as_uint(Asml[(kk + tg) * G1_PAD + r0]);
                as[mi][1] = __float_as_uint(Asml[(kk + tg) * G1_PAD + r0 + 8]);
                as[mi][2] = __float_as_uint(Asml[(kk + tg + 4) * G1_PAD + r0]);
                as[mi][3] = __float_as_uint(Asml[(kk + tg + 4) * G1_PAD + r0 + 8]);
            }
#pragma unroll
            for (int f = 0; f < 4; f++) {
                int n = nw * 32 + f * 8 + g;
                uint32_t bb0 = __float_as_uint(Bbig[(kk + tg) * G1_PAD + n]);
                uint32_t bb1 = __float_as_uint(Bbig[(kk + tg + 4) * G1_PAD + n]);
                uint32_t bs0 = __float_as_uint(Bsml[(kk + tg) * G1_PAD + n]);
                uint32_t bs1 = __float_as_uint(Bsml[(kk + tg + 4) * G1_PAD + n]);
#pragma unroll
                for (int mi = 0; mi < 4; mi++) {
                    MMA_TF32(acc[mi][f], ab[mi][0], ab[mi][1], ab[mi][2], ab[mi][3], bb0, bb1);
                    MMA_TF32(acc[mi][f], as[mi][0], as[mi][1], as[mi][2], as[mi][3], bb0, bb1);
                    MMA_TF32(acc[mi][f], ab[mi][0], ab[mi][1], ab[mi][2], ab[mi][3], bs0, bs1);
                }
            }
        }
    }

#pragma unroll
    for (int f = 0; f < 4; f++) {
        const int c = j0 + nw * 32 + f * 8 + tg * 2;
        const float bw0 = bWp[c];
        const float bw1 = bWp[c + 1];
        const int h = c >> 8;
        const int o = c & 255;
#pragma unroll
        for (int mi = 0; mi < 4; mi++) {
            int r0 = m0 + mw * 64 + mi * 16 + g;
            int b0i = r0 >> 10, n0i = r0 & 1023;
            int r1 = r0 + 8;
            int b1i = r1 >> 10, n1i = r1 & 1023;
            float2 v0, v1;
            v0.x = acc[mi][f][0] + bw0; v0.y = acc[mi][f][1] + bw1;
            v1.x = acc[mi][f][2] + bw0; v1.y = acc[mi][f][3] + bw1;
            *(float2*)(g_Wh + (((size_t)(b0i * HH + h) * NN + n0i) * FOUT + o)) = v0;
            *(float2*)(g_Wh + (((size_t)(b1i * HH + h) * NN + n1i) * FOUT + o)) = v1;
        }
    }
}

// ---------------------------------------------------------------------------
// Kernel 2: ei / ejb projections (unchanged)
// ---------------------------------------------------------------------------
__global__ void __launch_bounds__(256) score_kernel(const float* __restrict__ a1,
                                                    const float* __restrict__ a2,
                                                    const float* __restrict__ bA)
{
    const int warp = threadIdx.x >> 5;
    const int lane = threadIdx.x & 31;
    const int row = blockIdx.x * 8 + warp;
    const int h = (row >> 10) & (HH - 1);

    const float4* wr = (const float4*)(g_Wh + (size_t)row * FOUT);
    const float4* p1 = (const float4*)(a1 + h * FOUT);
    const float4* p2 = (const float4*)(a2 + h * FOUT);

    float s1 = 0.f, s2 = 0.f;
#pragma unroll
    for (int u = 0; u < 2; u++) {
        float4 v = wr[lane + u * 32];
        float4 x = p1[lane + u * 32];
        float4 y = p2[lane + u * 32];
        s1 += v.x * x.x + v.y * x.y + v.z * x.z + v.w * x.w;
        s2 += v.x * y.x + v.y * y.y + v.z * y.z + v.w * y.w;
    }
#pragma unroll
    for (int off = 16; off > 0; off >>= 1) {
        s1 += __shfl_xor_sync(0xffffffffu, s1, off);
        s2 += __shfl_xor_sync(0xffffffffu, s2, off);
    }
    if (lane == 0) {
        g_ei[row] = s1;
        g_ejb[row] = s2 + bA[h];
    }
}

// ---------------------------------------------------------------------------
// Kernel 3: attention via mma.sync bf16 m16n8k16 (2x tf32 rate).
// Wh tile in smem as [j(32)][o(256)] bf16, 16B chunk swizzle c' = c ^ (j&7).
// B fragments via ldmatrix.x4.trans (mats: j0-7, j8-15 = kc0 b0/b1;
// j16-23, j24-31 = kc1 b0/b1). P packed to bf16x2 in A-fragment order.
// D-fragment layout identical to tf32 path -> epilogue unchanged.
// ---------------------------------------------------------------------------
#define BUFB_BYTES (32 * 512)                      // 16KB per buffer
#define ATTN_SMEM (2 * BUFB_BYTES + NN * 16 + 512) // 49664 B

__global__ void __launch_bounds__(512, 1) attn_mma_kernel(float* __restrict__ out)
{
    extern __shared__ char smc[];
    float4* equad = (float4*)(smc + 2 * BUFB_BYTES);          // 1024 x 16B
    float*  linv  = (float*)(smc + 2 * BUFB_BYTES + NN * 16); // [128]
    const uint32_t sbase = smem_u32(smc);

    const int tid  = threadIdx.x;
    const int lane = tid & 31;
    const int wid  = tid >> 5;
    const int mw   = wid & 7;
    const int nw   = wid >> 3;
    const int g    = lane >> 2;
    const int tg   = lane & 3;
    const int bh   = blockIdx.x >> 3;
    const int it   = blockIdx.x & 7;

    // --- prologue: ej quads ---
    const float* ejg = g_ejb + (size_t)bh * NN;
#pragma unroll
    for (int q = 0; q < 2; q++) {
        int j = tid + q * 512;
        float e = ejg[j];
        equad[j] = make_float4(e, __expf(e), __expf(ALPHA * e), 0.f);
    }

    const int r1 = mw * 16 + g;
    const float ei1 = g_ei[(size_t)bh * NN + it * 128 + r1];
    const float ei2 = g_ei[(size_t)bh * NN + it * 128 + r1 + 8];
    const float Ai1 = __expf(ei1), Bi1 = __expf(ALPHA * ei1);
    const float Ai2 = __expf(ei2), Bi2 = __expf(ALPHA * ei2);

    float acc[16][4];
#pragma unroll
    for (int f = 0; f < 16; f++)
#pragma unroll
        for (int c = 0; c < 4; c++) acc[f][c] = 0.f;

    // --- loader mapping: warp = j row (jr, jr+16), lane = 8-o chunk ---
    const float* whbh = g_Wh + (size_t)bh * NN * FOUT;
    const int jr = wid;          // 0..15
    const int oc = lane;         // 0..31

    float4 st[4];
#pragma unroll
    for (int r = 0; r < 2; r++) {
        const float* src = whbh + (size_t)(jr + 16 * r) * FOUT + oc * 8;
        st[2 * r]     = *(const float4*)(src);
        st[2 * r + 1] = *(const float4*)(src + 4);
    }
#pragma unroll
    for (int r = 0; r < 2; r++) {
        int j = jr + 16 * r;
        uint32_t p0, p1, p2, p3;
        PACK_BF16X2(p0, st[2 * r].x, st[2 * r].y);
        PACK_BF16X2(p1, st[2 * r].z, st[2 * r].w);
        PACK_BF16X2(p2, st[2 * r + 1].x, st[2 * r + 1].y);
        PACK_BF16X2(p3, st[2 * r + 1].z, st[2 * r + 1].w);
        uint32_t addr = sbase + j * 512 + ((oc ^ (j & 7)) * 16);
        asm volatile("st.shared.v4.b32 [%0], {%1,%2,%3,%4};"
                     :: "r"(addr), "r"(p0), "r"(p1), "r"(p2), "r"(p3) : "memory");
    }
    __syncthreads();

    float lsum1 = 0.f, lsum2 = 0.f;

    for (int jt = 0; jt < 32; jt++) {
        const int cur = jt & 1;
        if (jt < 31) {
#pragma unroll
            for (int r = 0; r < 2; r++) {
                const float* src = whbh + (size_t)((jt + 1) * 32 + jr + 16 * r) * FOUT + oc * 8;
                st[2 * r]     = *(const float4*)(src);
                st[2 * r + 1] = *(const float4*)(src + 4);
            }
        }

        // --- P fragments (bf16x2, A-layout for m16n8k16) ---
        uint32_t aP[2][4];
#pragma unroll
        for (int s = 0; s < 4; s++) {
            int jl = jt * 32 + 2 * tg + 8 * s;
            float4 q0 = equad[jl];
            float4 q1 = equad[jl + 1];
            float e, pa1, pb1, pa2, pb2;
            e = ei1 + q0.x; pa1 = (e > 0.f) ? Ai1 * q0.y : Bi1 * q0.z;
            e = ei1 + q1.x; pb1 = (e > 0.f) ? Ai1 * q1.y : Bi1 * q1.z;
            e = ei2 + q0.x; pa2 = (e > 0.f) ? Ai2 * q0.y : Bi2 * q0.z;
            e = ei2 + q1.x; pb2 = (e > 0.f) ? Ai2 * q1.y : Bi2 * q1.z;
            if (nw == 0) { lsum1 += pa1 + pb1; lsum2 += pa2 + pb2; }
            uint32_t u1, u2;
            PACK_BF16X2(u1, pa1, pb1);
            PACK_BF16X2(u2, pa2, pb2);
            int kc = s >> 1;
            if ((s & 1) == 0) { aP[kc][0] = u1; aP[kc][1] = u2; }
            else              { aP[kc][2] = u1; aP[kc][3] = u2; }
        }

        // --- MMAs: 16 o-blocks, ldmatrix.x4.trans per block ---
        const uint32_t bufa = sbase + cur * BUFB_BYTES + lane * 512;
        const int key = lane & 7;
#pragma unroll
        for (int f = 0; f < 16; f++) {
            int c = nw * 16 + f;
            uint32_t b0, b1, b2, b3;
            ldsm_x4_t(b0, b1, b2, b3, bufa + ((c ^ key) * 16));
            MMA_BF16(acc[f], aP[0][0], aP[0][1], aP[0][2], aP[0][3], b0, b1);
            MMA_BF16(acc[f], aP[1][0], aP[1][1], aP[1][2], aP[1][3], b2, b3);
        }

        if (jt < 31) {
            const uint32_t nb = sbase + (cur ^ 1) * BUFB_BYTES;
#pragma unroll
            for (int r = 0; r < 2; r++) {
                int j = jr + 16 * r;
                uint32_t p0, p1, p2, p3;
                PACK_BF16X2(p0, st[2 * r].x, st[2 * r].y);
                PACK_BF16X2(p1, st[2 * r].z, st[2 * r].w);
                PACK_BF16X2(p2, st[2 * r + 1].x, st[2 * r + 1].y);
                PACK_BF16X2(p3, st[2 * r + 1].z, st[2 * r + 1].w);
                uint32_t addr = nb + j * 512 + ((oc ^ (j & 7)) * 16);
                asm volatile("st.shared.v4.b32 [%0], {%1,%2,%3,%4};"
                             :: "r"(addr), "r"(p0), "r"(p1), "r"(p2), "r"(p3) : "memory");
            }
        }
        __syncthreads();
    }

    // --- l reduction ---
    if (nw == 0) {
        lsum1 += __shfl_xor_sync(0xffffffffu, lsum1, 1);
        lsum1 += __shfl_xor_sync(0xffffffffu, lsum1, 2);
        lsum2 += __shfl_xor_sync(0xffffffffu, lsum2, 1);
        lsum2 += __shfl_xor_sync(0xffffffffu, lsum2, 2);
        if (tg == 0) {
            linv[r1] = 1.f / lsum1;
            linv[r1 + 8] = 1.f / lsum2;
        }
    }
    __syncthreads();

    const float li1 = linv[r1];
    const float li2 = linv[r1 + 8];
    const int b = bh >> 3, h = bh & 7;
    float* o1 = out + (size_t)(b * NN + it * 128 + r1) * (HH * FOUT)
                    + h * FOUT + nw * 128;
    float* o2 = o1 + (size_t)8 * (HH * FOUT);

#pragma unroll
    for (int f = 0; f < 16; f++) {
        int oc2 = f * 8 + tg * 2;
        float x0 = fmaxf(acc[f][0] * li1, 0.f);
        float x1 = fmaxf(acc[f][1] * li1, 0.f);
        float x2 = fmaxf(acc[f][2] * li2, 0.f);
        float x3 = fmaxf(acc[f][3] * li2, 0.f);
        float2 v1, v2;
        v1.x = 1.f / (1.f + __expf(-x0));
        v1.y = 1.f / (1.f + __expf(-x1));
        v2.x = 1.f / (1.f + __expf(-x2));
        v2.y = 1.f / (1.f + __expf(-x3));
        *(float2*)(o1 + oc2) = v1;
        *(float2*)(o2 + oc2) = v2;
    }
}

// ---------------------------------------------------------------------------
extern "C" void kernel_launch(void* const* d_in, const int* in_sizes, int n_in,
                              void* d_out, int out_size)
{
    (void)in_sizes; (void)n_in; (void)out_size;
    const float* h_in = (const float*)d_in[0];
    const float* W    = (const float*)d_in[1];
    const float* bW   = (const float*)d_in[2];
    const float* a1   = (const float*)d_in[3];
    const float* a2   = (const float*)d_in[4];
    const float* bA   = (const float*)d_in[5];
    float* out = (float*)d_out;

    cudaFuncSetAttribute(gemm1_tc_kernel,
                         cudaFuncAttributeMaxDynamicSharedMemorySize, G1_SMEM);
    gemm1_tc_kernel<<<dim3(128, 16), 256, G1_SMEM>>>(h_in, W, bW);

    score_kernel<<<(BB * HH * NN) / 8, 256>>>(a1, a2, bA);

    cudaFuncSetAttribute(attn_mma_kernel,
                         cudaFuncAttributeMaxDynamicSharedMemorySize, ATTN_SMEM);
    attn_mma_kernel<<<BB * HH * (NN / 128), 512, ATTN_SMEM>>>(out);
}

// round 7
// speedup vs baseline: 6.4189x; 1.1843x over previous
#include <cuda_runtime.h>
#include <cuda_bf16.h>
#include <stdint.h>
#include <math.h>

#define BB 16
#define NN 1024
#define FIN 256
#define FOUT 256
#define HH 8
#define ALPHA 0.2f

// Scratch (device globals; no allocations allowed)
__device__ float g_Wh[(size_t)BB * HH * NN * FOUT];   // [bh][n][o]
__device__ float g_ei[BB * HH * NN];                  // a1 . Wh_i
__device__ float g_ejb[BB * HH * NN];                 // a2 . Wh_j + bA[h]

#define MMA_BF16(c, a0, a1, a2, a3, b0, b1) \
    asm volatile("mma.sync.aligned.m16n8k16.row.col.f32.bf16.bf16.f32 " \
        "{%0,%1,%2,%3}, {%4,%5,%6,%7}, {%8,%9}, {%0,%1,%2,%3};" \
        : "+f"((c)[0]), "+f"((c)[1]), "+f"((c)[2]), "+f"((c)[3]) \
        : "r"(a0), "r"(a1), "r"(a2), "r"(a3), "r"(b0), "r"(b1))

// pack two fp32 -> bf16x2 (lo in low half)
#define PACK_BF16X2(r, lo, hi) \
    asm("cvt.rn.bf16x2.f32 %0, %1, %2;" : "=r"(r) : "f"(hi), "f"(lo))

__device__ __forceinline__ uint32_t smem_u32(const void* p) {
    uint32_t a;
    asm("{ .reg .u64 t; cvta.to.shared.u64 t, %1; cvt.u32.u64 %0, t; }"
        : "=r"(a) : "l"(p));
    return a;
}
__device__ __forceinline__ void ldsm_x4(uint32_t& r0, uint32_t& r1,
                                        uint32_t& r2, uint32_t& r3, uint32_t addr) {
    asm volatile("ldmatrix.sync.aligned.m8n8.x4.shared.b16 "
                 "{%0,%1,%2,%3}, [%4];"
                 : "=r"(r0), "=r"(r1), "=r"(r2), "=r"(r3) : "r"(addr));
}
__device__ __forceinline__ void ldsm_x4_t(uint32_t& r0, uint32_t& r1,
                                          uint32_t& r2, uint32_t& r3, uint32_t addr) {
    asm volatile("ldmatrix.sync.aligned.m8n8.x4.trans.shared.b16 "
                 "{%0,%1,%2,%3}, [%4];"
                 : "=r"(r0), "=r"(r1), "=r"(r2), "=r"(r3) : "r"(addr));
}

// big/small bf16 split of a float
__device__ __forceinline__ void split_bf16(float x, float& bigf, float& smlf) {
    __nv_bfloat16 b = __float2bfloat16(x);
    bigf = __bfloat162float(b);
    smlf = x - bigf;
}

// ---------------------------------------------------------------------------
// Kernel 1: Wh = h @ W^T + bW via 3xBF16 m16n8k16 + ldmatrix.
// CTA 128x128xK256 (8 k-tiles of 32). 256 thr = 8 warps: mw=wid&1, nw=wid>>1.
// smem planes (bf16): Abig/Asml/Bbig/Bsml, each [128 rows][32 k], 64B rows,
// chunk swizzle c' = c ^ (row&3) ^ ((row>>2)&3)  (conflict-free STS + LDSM).
// ---------------------------------------------------------------------------
#define G1_PLANE_B 8192
#define G1_SMEM (4 * G1_PLANE_B)

__global__ void __launch_bounds__(256, 2) gemm1_bf_kernel(const float* __restrict__ A,
                                                          const float* __restrict__ Wf,
                                                          const float* __restrict__ bWp)
{
    extern __shared__ char gsm[];
    const uint32_t sAb = smem_u32(gsm);
    const uint32_t sAs = sAb + G1_PLANE_B;
    const uint32_t sBb = sAb + 2 * G1_PLANE_B;
    const uint32_t sBs = sAb + 3 * G1_PLANE_B;

    const int tid  = threadIdx.x;
    const int lane = tid & 31;
    const int wid  = tid >> 5;
    const int mw   = wid & 1;
    const int nw   = wid >> 1;
    const int tg   = lane & 3;
    const int g    = lane >> 2;
    const int m0   = blockIdx.x * 128;
    const int j0   = blockIdx.y * 128;

    // loader mapping
    const int lrow = tid & 127;
    const int kh   = tid >> 7;                       // 0/1 -> chunks 2kh, 2kh+1
    const int swzr = (lrow & 3) ^ ((lrow >> 2) & 3);
    const uint32_t rbase = (uint32_t)lrow * 64;
    const uint32_t adr_c0 = rbase + (((2 * kh)     ^ swzr) << 4);
    const uint32_t adr_c1 = rbase + (((2 * kh + 1) ^ swzr) << 4);

    // ldmatrix lane mapping (same for A and B)
    const int lro  = (lane & 7) + ((lane >> 3) & 1) * 8;  // row offset 0..15
    const int lkc  = lane >> 4;                           // 0/1
    const int swzL = (lro & 3) ^ ((lro >> 2) & 3);

    float acc[4][4][4];
#pragma unroll
    for (int mi = 0; mi < 4; mi++)
#pragma unroll
        for (int f = 0; f < 4; f++)
#pragma unroll
            for (int c = 0; c < 4; c++) acc[mi][f][c] = 0.f;

    const float* apr = A  + (size_t)(m0 + lrow) * FIN + kh * 16;
    const float* bpr = Wf + (size_t)(j0 + lrow) * FIN + kh * 16;

    for (int kt = 0; kt < 8; kt++) {
        float xa[16], xb[16];
#pragma unroll
        for (int q = 0; q < 4; q++) {
            float4 va = *(const float4*)(apr + kt * 32 + q * 4);
            float4 vb = *(const float4*)(bpr + kt * 32 + q * 4);
            xa[q*4+0]=va.x; xa[q*4+1]=va.y; xa[q*4+2]=va.z; xa[q*4+3]=va.w;
            xb[q*4+0]=vb.x; xb[q*4+1]=vb.y; xb[q*4+2]=vb.z; xb[q*4+3]=vb.w;
        }
        __syncthreads();
        // split + pack + store (2 chunks per plane per operand)
#pragma unroll
        for (int hc = 0; hc < 2; hc++) {   // half-chunk: elems 8hc..8hc+7
            uint32_t pab[4], pas[4], pbb[4], pbs[4];
#pragma unroll
            for (int e = 0; e < 4; e++) {
                float b0, s0, b1, s1;
                split_bf16(xa[hc*8 + 2*e],     b0, s0);
                split_bf16(xa[hc*8 + 2*e + 1], b1, s1);
                PACK_BF16X2(pab[e], b0, b1);
                PACK_BF16X2(pas[e], s0, s1);
                split_bf16(xb[hc*8 + 2*e],     b0, s0);
                split_bf16(xb[hc*8 + 2*e + 1], b1, s1);
                PACK_BF16X2(pbb[e], b0, b1);
                PACK_BF16X2(pbs[e], s0, s1);
            }
            uint32_t off = hc ? adr_c1 : adr_c0;
            asm volatile("st.shared.v4.b32 [%0], {%1,%2,%3,%4};"
                :: "r"(sAb + off), "r"(pab[0]), "r"(pab[1]), "r"(pab[2]), "r"(pab[3]) : "memory");
            asm volatile("st.shared.v4.b32 [%0], {%1,%2,%3,%4};"
                :: "r"(sAs + off), "r"(pas[0]), "r"(pas[1]), "r"(pas[2]), "r"(pas[3]) : "memory");
            asm volatile("st.shared.v4.b32 [%0], {%1,%2,%3,%4};"
                :: "r"(sBb + off), "r"(pbb[0]), "r"(pbb[1]), "r"(pbb[2]), "r"(pbb[3]) : "memory");
            asm volatile("st.shared.v4.b32 [%0], {%1,%2,%3,%4};"
                :: "r"(sBs + off), "r"(pbs[0]), "r"(pbs[1]), "r"(pbs[2]), "r"(pbs[3]) : "memory");
        }
        __syncthreads();

#pragma unroll
        for (int ks = 0; ks < 2; ks++) {
            const int kc = 2 * ks + lkc;
            const uint32_t csw = (uint32_t)((kc ^ swzL) << 4);

            uint32_t ab[4][4], as_[4][4];
#pragma unroll
            for (int mi = 0; mi < 4; mi++) {
                uint32_t ro = (uint32_t)(mw * 64 + mi * 16 + lro) * 64 + csw;
                ldsm_x4(ab[mi][0], ab[mi][1], ab[mi][2], ab[mi][3], sAb + ro);
                ldsm_x4(as_[mi][0], as_[mi][1], as_[mi][2], as_[mi][3], sAs + ro);
            }
            uint32_t bbg[2][4], bsm[2][4];
#pragma unroll
            for (int fp = 0; fp < 2; fp++) {
                uint32_t ro = (uint32_t)(nw * 32 + fp * 16 + lro) * 64 + csw;
                ldsm_x4(bbg[fp][0], bbg[fp][1], bbg[fp][2], bbg[fp][3], sBb + ro);
                ldsm_x4(bsm[fp][0], bsm[fp][1], bsm[fp][2], bsm[fp][3], sBs + ro);
            }
#pragma unroll
            for (int fp = 0; fp < 2; fp++) {
#pragma unroll
                for (int sub = 0; sub < 2; sub++) {
                    const int f = fp * 2 + sub;
                    const uint32_t b0g = bbg[fp][sub],     b1g = bbg[fp][2 + sub];
                    const uint32_t b0s = bsm[fp][sub],     b1s = bsm[fp][2 + sub];
#pragma unroll
                    for (int mi = 0; mi < 4; mi++) {
                        MMA_BF16(acc[mi][f], ab[mi][0], ab[mi][1], ab[mi][2], ab[mi][3], b0g, b1g);
                        MMA_BF16(acc[mi][f], as_[mi][0], as_[mi][1], as_[mi][2], as_[mi][3], b0g, b1g);
                        MMA_BF16(acc[mi][f], ab[mi][0], ab[mi][1], ab[mi][2], ab[mi][3], b0s, b1s);
                    }
                }
            }
        }
    }

    // --- epilogue: + bias, scatter to g_Wh[b][h][n][o] (same D layout) ---
#pragma unroll
    for (int f = 0; f < 4; f++) {
        const int c = j0 + nw * 32 + f * 8 + tg * 2;
        const float bw0 = bWp[c];
        const float bw1 = bWp[c + 1];
        const int h = c >> 8;
        const int o = c & 255;
#pragma unroll
        for (int mi = 0; mi < 4; mi++) {
            int r0 = m0 + mw * 64 + mi * 16 + g;
            int b0i = r0 >> 10, n0i = r0 & 1023;
            int r1 = r0 + 8;
            int b1i = r1 >> 10, n1i = r1 & 1023;
            float2 v0, v1;
            v0.x = acc[mi][f][0] + bw0; v0.y = acc[mi][f][1] + bw1;
            v1.x = acc[mi][f][2] + bw0; v1.y = acc[mi][f][3] + bw1;
            *(float2*)(g_Wh + (((size_t)(b0i * HH + h) * NN + n0i) * FOUT + o)) = v0;
            *(float2*)(g_Wh + (((size_t)(b1i * HH + h) * NN + n1i) * FOUT + o)) = v1;
        }
    }
}

// ---------------------------------------------------------------------------
// Kernel 2: ei / ejb projections (unchanged)
// ---------------------------------------------------------------------------
__global__ void __launch_bounds__(256) score_kernel(const float* __restrict__ a1,
                                                    const float* __restrict__ a2,
                                                    const float* __restrict__ bA)
{
    const int warp = threadIdx.x >> 5;
    const int lane = threadIdx.x & 31;
    const int row = blockIdx.x * 8 + warp;
    const int h = (row >> 10) & (HH - 1);

    const float4* wr = (const float4*)(g_Wh + (size_t)row * FOUT);
    const float4* p1 = (const float4*)(a1 + h * FOUT);
    const float4* p2 = (const float4*)(a2 + h * FOUT);

    float s1 = 0.f, s2 = 0.f;
#pragma unroll
    for (int u = 0; u < 2; u++) {
        float4 v = wr[lane + u * 32];
        float4 x = p1[lane + u * 32];
        float4 y = p2[lane + u * 32];
        s1 += v.x * x.x + v.y * x.y + v.z * x.z + v.w * x.w;
        s2 += v.x * y.x + v.y * y.y + v.z * y.z + v.w * y.w;
    }
#pragma unroll
    for (int off = 16; off > 0; off >>= 1) {
        s1 += __shfl_xor_sync(0xffffffffu, s1, off);
        s2 += __shfl_xor_sync(0xffffffffu, s2, off);
    }
    if (lane == 0) {
        g_ei[row] = s1;
        g_ejb[row] = s2 + bA[h];
    }
}

// ---------------------------------------------------------------------------
// Kernel 3: attention via mma.sync bf16 m16n8k16 (unchanged from R6)
// ---------------------------------------------------------------------------
#define BUFB_BYTES (32 * 512)
#define ATTN_SMEM (2 * BUFB_BYTES + NN * 16 + 512)

__global__ void __launch_bounds__(512, 1) attn_mma_kernel(float* __restrict__ out)
{
    extern __shared__ char smc[];
    float4* equad = (float4*)(smc + 2 * BUFB_BYTES);
    float*  linv  = (float*)(smc + 2 * BUFB_BYTES + NN * 16);
    const uint32_t sbase = smem_u32(smc);

    const int tid  = threadIdx.x;
    const int lane = tid & 31;
    const int wid  = tid >> 5;
    const int mw   = wid & 7;
    const int nw   = wid >> 3;
    const int g    = lane >> 2;
    const int tg   = lane & 3;
    const int bh   = blockIdx.x >> 3;
    const int it   = blockIdx.x & 7;

    const float* ejg = g_ejb + (size_t)bh * NN;
#pragma unroll
    for (int q = 0; q < 2; q++) {
        int j = tid + q * 512;
        float e = ejg[j];
        equad[j] = make_float4(e, __expf(e), __expf(ALPHA * e), 0.f);
    }

    const int r1 = mw * 16 + g;
    const float ei1 = g_ei[(size_t)bh * NN + it * 128 + r1];
    const float ei2 = g_ei[(size_t)bh * NN + it * 128 + r1 + 8];
    const float Ai1 = __expf(ei1), Bi1 = __expf(ALPHA * ei1);
    const float Ai2 = __expf(ei2), Bi2 = __expf(ALPHA * ei2);

    float acc[16][4];
#pragma unroll
    for (int f = 0; f < 16; f++)
#pragma unroll
        for (int c = 0; c < 4; c++) acc[f][c] = 0.f;

    const float* whbh = g_Wh + (size_t)bh * NN * FOUT;
    const int jr = wid;
    const int oc = lane;

    float4 st[4];
#pragma unroll
    for (int r = 0; r < 2; r++) {
        const float* src = whbh + (size_t)(jr + 16 * r) * FOUT + oc * 8;
        st[2 * r]     = *(const float4*)(src);
        st[2 * r + 1] = *(const float4*)(src + 4);
    }
#pragma unroll
    for (int r = 0; r < 2; r++) {
        int j = jr + 16 * r;
        uint32_t p0, p1, p2, p3;
        PACK_BF16X2(p0, st[2 * r].x, st[2 * r].y);
        PACK_BF16X2(p1, st[2 * r].z, st[2 * r].w);
        PACK_BF16X2(p2, st[2 * r + 1].x, st[2 * r + 1].y);
        PACK_BF16X2(p3, st[2 * r + 1].z, st[2 * r + 1].w);
        uint32_t addr = sbase + j * 512 + ((oc ^ (j & 7)) * 16);
        asm volatile("st.shared.v4.b32 [%0], {%1,%2,%3,%4};"
                     :: "r"(addr), "r"(p0), "r"(p1), "r"(p2), "r"(p3) : "memory");
    }
    __syncthreads();

    float lsum1 = 0.f, lsum2 = 0.f;

    for (int jt = 0; jt < 32; jt++) {
        const int cur = jt & 1;
        if (jt < 31) {
#pragma unroll
            for (int r = 0; r < 2; r++) {
                const float* src = whbh + (size_t)((jt + 1) * 32 + jr + 16 * r) * FOUT + oc * 8;
                st[2 * r]     = *(const float4*)(src);
                st[2 * r + 1] = *(const float4*)(src + 4);
            }
        }

        uint32_t aP[2][4];
#pragma unroll
        for (int s = 0; s < 4; s++) {
            int jl = jt * 32 + 2 * tg + 8 * s;
            float4 q0 = equad[jl];
            float4 q1 = equad[jl + 1];
            float e, pa1, pb1, pa2, pb2;
            e = ei1 + q0.x; pa1 = (e > 0.f) ? Ai1 * q0.y : Bi1 * q0.z;
            e = ei1 + q1.x; pb1 = (e > 0.f) ? Ai1 * q1.y : Bi1 * q1.z;
            e = ei2 + q0.x; pa2 = (e > 0.f) ? Ai2 * q0.y : Bi2 * q0.z;
            e = ei2 + q1.x; pb2 = (e > 0.f) ? Ai2 * q1.y : Bi2 * q1.z;
            if (nw == 0) { lsum1 += pa1 + pb1; lsum2 += pa2 + pb2; }
            uint32_t u1, u2;
            PACK_BF16X2(u1, pa1, pb1);
            PACK_BF16X2(u2, pa2, pb2);
            int kc = s >> 1;
            if ((s & 1) == 0) { aP[kc][0] = u1; aP[kc][1] = u2; }
            else              { aP[kc][2] = u1; aP[kc][3] = u2; }
        }

        const uint32_t bufa = sbase + cur * BUFB_BYTES + lane * 512;
        const int key = lane & 7;
#pragma unroll
        for (int f = 0; f < 16; f++) {
            int c = nw * 16 + f;
            uint32_t b0, b1, b2, b3;
            ldsm_x4_t(b0, b1, b2, b3, bufa + ((c ^ key) * 16));
            MMA_BF16(acc[f], aP[0][0], aP[0][1], aP[0][2], aP[0][3], b0, b1);
            MMA_BF16(acc[f], aP[1][0], aP[1][1], aP[1][2], aP[1][3], b2, b3);
        }

        if (jt < 31) {
            const uint32_t nb = sbase + (cur ^ 1) * BUFB_BYTES;
#pragma unroll
            for (int r = 0; r < 2; r++) {
                int j = jr + 16 * r;
                uint32_t p0, p1, p2, p3;
                PACK_BF16X2(p0, st[2 * r].x, st[2 * r].y);
                PACK_BF16X2(p1, st[2 * r].z, st[2 * r].w);
                PACK_BF16X2(p2, st[2 * r + 1].x, st[2 * r + 1].y);
                PACK_BF16X2(p3, st[2 * r + 1].z, st[2 * r + 1].w);
                uint32_t addr = nb + j * 512 + ((oc ^ (j & 7)) * 16);
                asm volatile("st.shared.v4.b32 [%0], {%1,%2,%3,%4};"
                             :: "r"(addr), "r"(p0), "r"(p1), "r"(p2), "r"(p3) : "memory");
            }
        }
        __syncthreads();
    }

    if (nw == 0) {
        lsum1 += __shfl_xor_sync(0xffffffffu, lsum1, 1);
        lsum1 += __shfl_xor_sync(0xffffffffu, lsum1, 2);
        lsum2 += __shfl_xor_sync(0xffffffffu, lsum2, 1);
        lsum2 += __shfl_xor_sync(0xffffffffu, lsum2, 2);
        if (tg == 0) {
            linv[r1] = 1.f / lsum1;
            linv[r1 + 8] = 1.f / lsum2;
        }
    }
    __syncthreads();

    const float li1 = linv[r1];
    const float li2 = linv[r1 + 8];
    const int b = bh >> 3, h = bh & 7;
    float* o1 = out + (size_t)(b * NN + it * 128 + r1) * (HH * FOUT)
                    + h * FOUT + nw * 128;
    float* o2 = o1 + (size_t)8 * (HH * FOUT);

#pragma unroll
    for (int f = 0; f < 16; f++) {
        int oc2 = f * 8 + tg * 2;
        float x0 = fmaxf(acc[f][0] * li1, 0.f);
        float x1 = fmaxf(acc[f][1] * li1, 0.f);
        float x2 = fmaxf(acc[f][2] * li2, 0.f);
        float x3 = fmaxf(acc[f][3] * li2, 0.f);
        float2 v1, v2;
        v1.x = 1.f / (1.f + __expf(-x0));
        v1.y = 1.f / (1.f + __expf(-x1));
        v2.x = 1.f / (1.f + __expf(-x2));
        v2.y = 1.f / (1.f + __expf(-x3));
        *(float2*)(o1 + oc2) = v1;
        *(float2*)(o2 + oc2) = v2;
    }
}

// ---------------------------------------------------------------------------
extern "C" void kernel_launch(void* const* d_in, const int* in_sizes, int n_in,
                              void* d_out, int out_size)
{
    (void)in_sizes; (void)n_in; (void)out_size;
    const float* h_in = (const float*)d_in[0];
    const float* W    = (const float*)d_in[1];
    const float* bW   = (const float*)d_in[2];
    const float* a1   = (const float*)d_in[3];
    const float* a2   = (const float*)d_in[4];
    const float* bA   = (const float*)d_in[5];
    float* out = (float*)d_out;

    cudaFuncSetAttribute(gemm1_bf_kernel,
                         cudaFuncAttributeMaxDynamicSharedMemorySize, G1_SMEM);
    gemm1_bf_kernel<<<dim3(128, 16), 256, G1_SMEM>>>(h_in, W, bW);

    score_kernel<<<(BB * HH * NN) / 8, 256>>>(a1, a2, bA);

    cudaFuncSetAttribute(attn_mma_kernel,
                         cudaFuncAttributeMaxDynamicSharedMemorySize, ATTN_SMEM);
    attn_mma_kernel<<<BB * HH * (NN / 128), 512, ATTN_SMEM>>>(out);
}

// round 8
// speedup vs baseline: 7.8897x; 1.2291x over previous
#include <cuda_runtime.h>
#include <cuda_bf16.h>
#include <stdint.h>
#include <math.h>

#define BB 16
#define NN 1024
#define FIN 256
#define FOUT 256
#define HH 8
#define ALPHA 0.2f

// Scratch (device globals; no allocations allowed)
__device__ float g_Wh[(size_t)BB * HH * NN * FOUT];        // [bh][n][o] fp32
__device__ __nv_bfloat16 g_Whb[(size_t)BB * HH * NN * FOUT]; // bf16 copy
__device__ float g_ei[BB * HH * NN];
__device__ float g_ejb[BB * HH * NN];
// pre-split bf16 operand planes, k-tiled: [kt(8)][row][32k]
__device__ __nv_bfloat16 g_hb[(size_t)8 * 16384 * 32];
__device__ __nv_bfloat16 g_hs[(size_t)8 * 16384 * 32];
__device__ __nv_bfloat16 g_wb[(size_t)8 * 2048 * 32];
__device__ __nv_bfloat16 g_ws[(size_t)8 * 2048 * 32];

#define MMA_BF16(c, a0, a1, a2, a3, b0, b1) \
    asm volatile("mma.sync.aligned.m16n8k16.row.col.f32.bf16.bf16.f32 " \
        "{%0,%1,%2,%3}, {%4,%5,%6,%7}, {%8,%9}, {%0,%1,%2,%3};" \
        : "+f"((c)[0]), "+f"((c)[1]), "+f"((c)[2]), "+f"((c)[3]) \
        : "r"(a0), "r"(a1), "r"(a2), "r"(a3), "r"(b0), "r"(b1))

#define PACK_BF16X2(r, lo, hi) \
    asm("cvt.rn.bf16x2.f32 %0, %1, %2;" : "=r"(r) : "f"(hi), "f"(lo))

#define CP16(dst, src) \
    asm volatile("cp.async.cg.shared.global [%0], [%1], 16;" :: "r"(dst), "l"(src) : "memory")
#define CP_COMMIT() asm volatile("cp.async.commit_group;" ::: "memory")
#define CP_WAIT1()  asm volatile("cp.async.wait_group 1;" ::: "memory")
#define CP_WAIT0()  asm volatile("cp.async.wait_group 0;" ::: "memory")

__device__ __forceinline__ uint32_t smem_u32(const void* p) {
    uint32_t a;
    asm("{ .reg .u64 t; cvta.to.shared.u64 t, %1; cvt.u32.u64 %0, t; }"
        : "=r"(a) : "l"(p));
    return a;
}
__device__ __forceinline__ void ldsm_x4(uint32_t& r0, uint32_t& r1,
                                        uint32_t& r2, uint32_t& r3, uint32_t addr) {
    asm volatile("ldmatrix.sync.aligned.m8n8.x4.shared.b16 {%0,%1,%2,%3}, [%4];"
                 : "=r"(r0), "=r"(r1), "=r"(r2), "=r"(r3) : "r"(addr));
}
__device__ __forceinline__ void ldsm_x4_t(uint32_t& r0, uint32_t& r1,
                                          uint32_t& r2, uint32_t& r3, uint32_t addr) {
    asm volatile("ldmatrix.sync.aligned.m8n8.x4.trans.shared.b16 {%0,%1,%2,%3}, [%4];"
                 : "=r"(r0), "=r"(r1), "=r"(r2), "=r"(r3) : "r"(addr));
}

// ---------------------------------------------------------------------------
// Prep: split fp32 -> big/small bf16, k-tiled [kt][row][32]
// ---------------------------------------------------------------------------
__global__ void split_h_kernel(const float* __restrict__ src)
{
    const int m = blockIdx.x;          // 0..16383
    const int k = threadIdx.x;         // 0..255
    float x = src[(size_t)m * 256 + k];
    __nv_bfloat16 b = __float2bfloat16(x);
    __nv_bfloat16 s = __float2bfloat16(x - __bfloat162float(b));
    size_t idx = ((size_t)(k >> 5) * 16384 + m) * 32 + (k & 31);
    g_hb[idx] = b;
    g_hs[idx] = s;
}
__global__ void split_w_kernel(const float* __restrict__ src)
{
    const int j = blockIdx.x;          // 0..2047
    const int k = threadIdx.x;
    float x = src[(size_t)j * 256 + k];
    __nv_bfloat16 b = __float2bfloat16(x);
    __nv_bfloat16 s = __float2bfloat16(x - __bfloat162float(b));
    size_t idx = ((size_t)(k >> 5) * 2048 + j) * 32 + (k & 31);
    g_wb[idx] = b;
    g_ws[idx] = s;
}

// ---------------------------------------------------------------------------
// Kernel 1: Wh = h @ W^T + bW via 3xBF16 m16n8k16, cp.async 3-stage pipeline.
// smem: 3 bufs x [Abig|Asml|Bbig|Bsml] 8KB planes (rows 64B, chunk swizzle
// c' = c ^ (row&3) ^ ((row>>2)&3)). MMA phase identical to R7.
// Epilogue also writes g_Whb (bf16).
// ---------------------------------------------------------------------------
#define G1_PLANE_B 8192
#define G1_BUF (4 * G1_PLANE_B)        // 32KB
#define G1_SMEM (3 * G1_BUF)           // 96KB

__global__ void __launch_bounds__(256, 2) gemm1_cp_kernel(const float* __restrict__ bWp)
{
    extern __shared__ char gsm[];
    const uint32_t sbuf = smem_u32(gsm);

    const int tid  = threadIdx.x;
    const int lane = tid & 31;
    const int wid  = tid >> 5;
    const int mw   = wid & 1;
    const int nw   = wid >> 1;
    const int tg   = lane & 3;
    const int g    = lane >> 2;
    const int m0   = blockIdx.x * 128;
    const int j0   = blockIdx.y * 128;

    // loader mapping: thread -> (row, k-half); 2 chunks of 16B per plane
    const int lrow = tid & 127;
    const int kh   = tid >> 7;
    const int swzr = (lrow & 3) ^ ((lrow >> 2) & 3);
    const uint32_t d0 = (uint32_t)lrow * 64 + (((2 * kh)     ^ swzr) << 4);
    const uint32_t d1 = (uint32_t)lrow * 64 + (((2 * kh + 1) ^ swzr) << 4);
    const char* srcAb = (const char*)g_hb + ((size_t)(m0 + lrow)) * 64 + kh * 32;
    const char* srcAs = (const char*)g_hs + ((size_t)(m0 + lrow)) * 64 + kh * 32;
    const char* srcBb = (const char*)g_wb + ((size_t)(j0 + lrow)) * 64 + kh * 32;
    const char* srcBs = (const char*)g_ws + ((size_t)(j0 + lrow)) * 64 + kh * 32;

    // ldmatrix lane mapping
    const int lro  = (lane & 7) + ((lane >> 3) & 1) * 8;
    const int lkc  = lane >> 4;
    const int swzL = (lro & 3) ^ ((lro >> 2) & 3);

    float acc[4][4][4];
#pragma unroll
    for (int mi = 0; mi < 4; mi++)
#pragma unroll
        for (int f = 0; f < 4; f++)
#pragma unroll
            for (int c = 0; c < 4; c++) acc[mi][f][c] = 0.f;

    // stage kt=0
    {
        const uint32_t bb = sbuf;
        CP16(bb + d0, srcAb); CP16(bb + d1, srcAb + 16);
        CP16(bb + G1_PLANE_B + d0, srcAs); CP16(bb + G1_PLANE_B + d1, srcAs + 16);
        CP16(bb + 2 * G1_PLANE_B + d0, srcBb); CP16(bb + 2 * G1_PLANE_B + d1, srcBb + 16);
        CP16(bb + 3 * G1_PLANE_B + d0, srcBs); CP16(bb + 3 * G1_PLANE_B + d1, srcBs + 16);
        CP_COMMIT();
    }

    for (int kt = 0; kt < 8; kt++) {
        if (kt < 7) {
            const uint32_t bb = sbuf + ((kt + 1) % 3) * G1_BUF;
            const size_t offA = (size_t)(kt + 1) * (16384 * 64);
            const size_t offB = (size_t)(kt + 1) * (2048 * 64);
            CP16(bb + d0, srcAb + offA); CP16(bb + d1, srcAb + offA + 16);
            CP16(bb + G1_PLANE_B + d0, srcAs + offA); CP16(bb + G1_PLANE_B + d1, srcAs + offA + 16);
            CP16(bb + 2 * G1_PLANE_B + d0, srcBb + offB); CP16(bb + 2 * G1_PLANE_B + d1, srcBb + offB + 16);
            CP16(bb + 3 * G1_PLANE_B + d0, srcBs + offB); CP16(bb + 3 * G1_PLANE_B + d1, srcBs + offB + 16);
            CP_COMMIT();
            CP_WAIT1();
        } else {
            CP_WAIT0();
        }
        __syncthreads();

        const uint32_t base = sbuf + (kt % 3) * G1_BUF;
        const uint32_t sAb = base;
        const uint32_t sAs = base + G1_PLANE_B;
        const uint32_t sBb = base + 2 * G1_PLANE_B;
        const uint32_t sBs = base + 3 * G1_PLANE_B;

#pragma unroll
        for (int ks = 0; ks < 2; ks++) {
            const int kc = 2 * ks + lkc;
            const uint32_t csw = (uint32_t)((kc ^ swzL) << 4);

            uint32_t ab[4][4], as_[4][4];
#pragma unroll
            for (int mi = 0; mi < 4; mi++) {
                uint32_t ro = (uint32_t)(mw * 64 + mi * 16 + lro) * 64 + csw;
                ldsm_x4(ab[mi][0], ab[mi][1], ab[mi][2], ab[mi][3], sAb + ro);
                ldsm_x4(as_[mi][0], as_[mi][1], as_[mi][2], as_[mi][3], sAs + ro);
            }
            uint32_t bbg[2][4], bsm[2][4];
#pragma unroll
            for (int fp = 0; fp < 2; fp++) {
                uint32_t ro = (uint32_t)(nw * 32 + fp * 16 + lro) * 64 + csw;
                ldsm_x4(bbg[fp][0], bbg[fp][1], bbg[fp][2], bbg[fp][3], sBb + ro);
                ldsm_x4(bsm[fp][0], bsm[fp][1], bsm[fp][2], bsm[fp][3], sBs + ro);
            }
#pragma unroll
            for (int fp = 0; fp < 2; fp++) {
#pragma unroll
                for (int sub = 0; sub < 2; sub++) {
                    const int f = fp * 2 + sub;
                    const uint32_t b0g = bbg[fp][sub], b1g = bbg[fp][2 + sub];
                    const uint32_t b0s = bsm[fp][sub], b1s = bsm[fp][2 + sub];
#pragma unroll
                    for (int mi = 0; mi < 4; mi++) {
                        MMA_BF16(acc[mi][f], ab[mi][0], ab[mi][1], ab[mi][2], ab[mi][3], b0g, b1g);
                        MMA_BF16(acc[mi][f], as_[mi][0], as_[mi][1], as_[mi][2], as_[mi][3], b0g, b1g);
                        MMA_BF16(acc[mi][f], ab[mi][0], ab[mi][1], ab[mi][2], ab[mi][3], b0s, b1s);
                    }
                }
            }
        }
    }

    // --- epilogue: + bias -> g_Wh (fp32) and g_Whb (bf16) ---
#pragma unroll
    for (int f = 0; f < 4; f++) {
        const int c = j0 + nw * 32 + f * 8 + tg * 2;
        const float bw0 = bWp[c];
        const float bw1 = bWp[c + 1];
        const int h = c >> 8;
        const int o = c & 255;
#pragma unroll
        for (int mi = 0; mi < 4; mi++) {
            int r0 = m0 + mw * 64 + mi * 16 + g;
            int b0i = r0 >> 10, n0i = r0 & 1023;
            int r1 = r0 + 8;
            int b1i = r1 >> 10, n1i = r1 & 1023;
            float2 v0, v1;
            v0.x = acc[mi][f][0] + bw0; v0.y = acc[mi][f][1] + bw1;
            v1.x = acc[mi][f][2] + bw0; v1.y = acc[mi][f][3] + bw1;
            size_t i0 = ((size_t)(b0i * HH + h) * NN + n0i) * FOUT + o;
            size_t i1 = ((size_t)(b1i * HH + h) * NN + n1i) * FOUT + o;
            *(float2*)(g_Wh + i0) = v0;
            *(float2*)(g_Wh + i1) = v1;
            uint32_t u0, u1;
            PACK_BF16X2(u0, v0.x, v0.y);
            PACK_BF16X2(u1, v1.x, v1.y);
            *(uint32_t*)((char*)g_Whb + i0 * 2) = u0;
            *(uint32_t*)((char*)g_Whb + i1 * 2) = u1;
        }
    }
}

// ---------------------------------------------------------------------------
// Kernel 2: ei / ejb projections (unchanged)
// ---------------------------------------------------------------------------
__global__ void __launch_bounds__(256) score_kernel(const float* __restrict__ a1,
                                                    const float* __restrict__ a2,
                                                    const float* __restrict__ bA)
{
    const int warp = threadIdx.x >> 5;
    const int lane = threadIdx.x & 31;
    const int row = blockIdx.x * 8 + warp;
    const int h = (row >> 10) & (HH - 1);

    const float4* wr = (const float4*)(g_Wh + (size_t)row * FOUT);
    const float4* p1 = (const float4*)(a1 + h * FOUT);
    const float4* p2 = (const float4*)(a2 + h * FOUT);

    float s1 = 0.f, s2 = 0.f;
#pragma unroll
    for (int u = 0; u < 2; u++) {
        float4 v = wr[lane + u * 32];
        float4 x = p1[lane + u * 32];
        float4 y = p2[lane + u * 32];
        s1 += v.x * x.x + v.y * x.y + v.z * x.z + v.w * x.w;
        s2 += v.x * y.x + v.y * y.y + v.z * y.z + v.w * y.w;
    }
#pragma unroll
    for (int off = 16; off > 0; off >>= 1) {
        s1 += __shfl_xor_sync(0xffffffffu, s1, off);
        s2 += __shfl_xor_sync(0xffffffffu, s2, off);
    }
    if (lane == 0) {
        g_ei[row] = s1;
        g_ejb[row] = s2 + bA[h];
    }
}

// ---------------------------------------------------------------------------
// Kernel 3: attention, bf16 m16n8k16 + cp.async 3-stage B pipeline from g_Whb.
// B buffer layout identical to R6 ([j][512B], chunk swizzle c^(j&7)).
// ---------------------------------------------------------------------------
#define BUFB_BYTES 16384
#define ATTN_SMEM (3 * BUFB_BYTES + NN * 16 + 512)

__global__ void __launch_bounds__(512, 1) attn_cp_kernel(float* __restrict__ out)
{
    extern __shared__ char smc[];
    float4* equad = (float4*)(smc + 3 * BUFB_BYTES);
    float*  linv  = (float*)(smc + 3 * BUFB_BYTES + NN * 16);
    const uint32_t sbase = smem_u32(smc);

    const int tid  = threadIdx.x;
    const int lane = tid & 31;
    const int wid  = tid >> 5;
    const int mw   = wid & 7;
    const int nw   = wid >> 3;
    const int g    = lane >> 2;
    const int tg   = lane & 3;
    const int bh   = blockIdx.x >> 3;
    const int it   = blockIdx.x & 7;

    // loader mapping: thread -> (j, 2 chunks of 16B)
    const int ldj = tid >> 4;             // 0..31
    const int ldc = (tid & 15) * 2;       // chunks ldc, ldc+1
    const char* whbB = (const char*)g_Whb + (size_t)bh * (NN * FOUT) * 2;
    const uint32_t dA = (uint32_t)ldj * 512 + (((ldc)     ^ (ldj & 7)) << 4);
    const uint32_t dB = (uint32_t)ldj * 512 + (((ldc + 1) ^ (ldj & 7)) << 4);

    // stage jt=0
    {
        const char* s = whbB + ((size_t)ldj) * 512 + ldc * 16;
        CP16(sbase + dA, s);
        CP16(sbase + dB, s + 16);
        CP_COMMIT();
    }

    // --- prologue: ej quads ---
    const float* ejg = g_ejb + (size_t)bh * NN;
#pragma unroll
    for (int q = 0; q < 2; q++) {
        int j = tid + q * 512;
        float e = ejg[j];
        equad[j] = make_float4(e, __expf(e), __expf(ALPHA * e), 0.f);
    }

    const int r1 = mw * 16 + g;
    const float ei1 = g_ei[(size_t)bh * NN + it * 128 + r1];
    const float ei2 = g_ei[(size_t)bh * NN + it * 128 + r1 + 8];
    const float Ai1 = __expf(ei1), Bi1 = __expf(ALPHA * ei1);
    const float Ai2 = __expf(ei2), Bi2 = __expf(ALPHA * ei2);

    float acc[16][4];
#pragma unroll
    for (int f = 0; f < 16; f++)
#pragma unroll
        for (int c = 0; c < 4; c++) acc[f][c] = 0.f;

    __syncthreads();   // equad visible before first aP compute

    float lsum1 = 0.f, lsum2 = 0.f;

    for (int jt = 0; jt < 32; jt++) {
        if (jt < 31) {
            const uint32_t bb = sbase + ((jt + 1) % 3) * BUFB_BYTES;
            const char* s = whbB + ((size_t)(jt + 1) * 32 + ldj) * 512 + ldc * 16;
            CP16(bb + dA, s);
            CP16(bb + dB, s + 16);
            CP_COMMIT();
            CP_WAIT1();
        } else {
            CP_WAIT0();
        }

        // --- P fragments (independent of B buffers) ---
        uint32_t aP[2][4];
#pragma unroll
        for (int s = 0; s < 4; s++) {
            int jl = jt * 32 + 2 * tg + 8 * s;
            float4 q0 = equad[jl];
            float4 q1 = equad[jl + 1];
            float e, pa1, pb1, pa2, pb2;
            e = ei1 + q0.x; pa1 = (e > 0.f) ? Ai1 * q0.y : Bi1 * q0.z;
            e = ei1 + q1.x; pb1 = (e > 0.f) ? Ai1 * q1.y : Bi1 * q1.z;
            e = ei2 + q0.x; pa2 = (e > 0.f) ? Ai2 * q0.y : Bi2 * q0.z;
            e = ei2 + q1.x; pb2 = (e > 0.f) ? Ai2 * q1.y : Bi2 * q1.z;
            if (nw == 0) { lsum1 += pa1 + pb1; lsum2 += pa2 + pb2; }
            uint32_t u1, u2;
            PACK_BF16X2(u1, pa1, pb1);
            PACK_BF16X2(u2, pa2, pb2);
            int kc = s >> 1;
            if ((s & 1) == 0) { aP[kc][0] = u1; aP[kc][1] = u2; }
            else              { aP[kc][2] = u1; aP[kc][3] = u2; }
        }

        __syncthreads();   // buf[jt%3] complete + prior readers done

        const uint32_t bufa = sbase + (jt % 3) * BUFB_BYTES + lane * 512;
        const int key = lane & 7;
#pragma unroll
        for (int f = 0; f < 16; f++) {
            int c = nw * 16 + f;
            uint32_t b0, b1, b2, b3;
            ldsm_x4_t(b0, b1, b2, b3, bufa + ((c ^ key) * 16));
            MMA_BF16(acc[f], aP[0][0], aP[0][1], aP[0][2], aP[0][3], b0, b1);
            MMA_BF16(acc[f], aP[1][0], aP[1][1], aP[1][2], aP[1][3], b2, b3);
        }
    }

    // --- l reduction ---
    if (nw == 0) {
        lsum1 += __shfl_xor_sync(0xffffffffu, lsum1, 1);
        lsum1 += __shfl_xor_sync(0xffffffffu, lsum1, 2);
        lsum2 += __shfl_xor_sync(0xffffffffu, lsum2, 1);
        lsum2 += __shfl_xor_sync(0xffffffffu, lsum2, 2);
        if (tg == 0) {
            linv[r1] = 1.f / lsum1;
            linv[r1 + 8] = 1.f / lsum2;
        }
    }
    __syncthreads();

    const float li1 = linv[r1];
    const float li2 = linv[r1 + 8];
    const int b = bh >> 3, h = bh & 7;
    float* o1 = out + (size_t)(b * NN + it * 128 + r1) * (HH * FOUT)
                    + h * FOUT + nw * 128;
    float* o2 = o1 + (size_t)8 * (HH * FOUT);

#pragma unroll
    for (int f = 0; f < 16; f++) {
        int oc2 = f * 8 + tg * 2;
        float x0 = fmaxf(acc[f][0] * li1, 0.f);
        float x1 = fmaxf(acc[f][1] * li1, 0.f);
        float x2 = fmaxf(acc[f][2] * li2, 0.f);
        float x3 = fmaxf(acc[f][3] * li2, 0.f);
        float2 v1, v2;
        v1.x = 1.f / (1.f + __expf(-x0));
        v1.y = 1.f / (1.f + __expf(-x1));
        v2.x = 1.f / (1.f + __expf(-x2));
        v2.y = 1.f / (1.f + __expf(-x3));
        *(float2*)(o1 + oc2) = v1;
        *(float2*)(o2 + oc2) = v2;
    }
}

// ---------------------------------------------------------------------------
extern "C" void kernel_launch(void* const* d_in, const int* in_sizes, int n_in,
                              void* d_out, int out_size)
{
    (void)in_sizes; (void)n_in; (void)out_size;
    const float* h_in = (const float*)d_in[0];
    const float* W    = (const float*)d_in[1];
    const float* bW   = (const float*)d_in[2];
    const float* a1   = (const float*)d_in[3];
    const float* a2   = (const float*)d_in[4];
    const float* bA   = (const float*)d_in[5];
    float* out = (float*)d_out;

    split_h_kernel<<<16384, 256>>>(h_in);
    split_w_kernel<<<2048, 256>>>(W);

    cudaFuncSetAttribute(gemm1_cp_kernel,
                         cudaFuncAttributeMaxDynamicSharedMemorySize, G1_SMEM);
    gemm1_cp_kernel<<<dim3(128, 16), 256, G1_SMEM>>>(bW);

    score_kernel<<<(BB * HH * NN) / 8, 256>>>(a1, a2, bA);

    cudaFuncSetAttribute(attn_cp_kernel,
                         cudaFuncAttributeMaxDynamicSharedMemorySize, ATTN_SMEM);
    attn_cp_kernel<<<BB * HH * (NN / 128), 512, ATTN_SMEM>>>(out);
}